// round 2
// baseline (speedup 1.0000x reference)
#include <cuda_runtime.h>

#define BATCH   2
#define SEQ     1024
#define HEADS   8
#define DEP     64
#define NF      64
#define BH      (BATCH*HEADS)   // 16
#define DMODEL  512
#define CHUNK   64
#define NCH     (SEQ/CHUNK)     // 16
#define NROWS   (BATCH*SEQ*HEADS) // 16384 token-head rows

// ---------------- scratch (static device globals; no allocation) ----------------
__device__ float g_Mq[NF*DEP];
__device__ float g_Mk[NF*DEP];
__device__ float g_cbq[NF];
__device__ float g_cbk[NF];
__device__ float g_qf[BH*SEQ*NF];            // features of q; later overwritten with qt = qf/Kc
__device__ float g_kf[BH*SEQ*NF];
__device__ float g_vp[BH*SEQ*DEP];
__device__ float g_pS[BH*NCH*NF*DEP];        // per-chunk sum of kf ⊗ vp
__device__ float g_preS[BH*NCH*NF*DEP];      // exclusive prefix over chunks
__device__ float g_pK[BH*NCH*NF];            // per-chunk sum of kf
__device__ float g_preK[BH*NCH*NF];          // exclusive prefix
__device__ float g_attn[BATCH*SEQ*DMODEL];   // attention out, [b][s][h*64+d]

// ---------------- 4x4x4 fp32 micro-kernel ----------------
// C[rb+i][cb+j] += sum_kk A[(rb+i)*LDA + k+kk] * B[(k+kk)*LDB + cb+j]
template<int LDA, int LDB>
__device__ __forceinline__ void micro4(const float* As, const float* Bs,
                                       int rb, int cb, int k, float acc[4][4]) {
    float a[4][4], b[4][4];
#pragma unroll
    for (int i = 0; i < 4; i++)
        *(float4*)a[i] = *(const float4*)&As[(rb + i) * LDA + k];
#pragma unroll
    for (int kk = 0; kk < 4; kk++)
        *(float4*)b[kk] = *(const float4*)&Bs[(k + kk) * LDB + cb];
#pragma unroll
    for (int i = 0; i < 4; i++)
#pragma unroll
        for (int kk = 0; kk < 4; kk++)
#pragma unroll
            for (int j = 0; j < 4; j++)
                acc[i][j] = fmaf(a[i][kk], b[kk][j], acc[i][j]);
}

// ---------------- K0: fold Linear + ORF into one 64x64 matrix per stream ----------------
__global__ void prep_kernel(const float* __restrict__ Wq, const float* __restrict__ bq,
                            const float* __restrict__ Wk, const float* __restrict__ bk,
                            const float* __restrict__ orfq, const float* __restrict__ orfk) {
    const float norm = 0.35355339059327379f;  // 64^(-0.25)
    int tid = threadIdx.x;  // 256 threads
    for (int c = tid * 16; c < tid * 16 + 16; c++) {
        int f = c >> 6, d = c & 63;
        float aq = 0.f, ak = 0.f;
        for (int e = 0; e < 64; e++) {
            aq += orfq[f * 64 + e] * Wq[e * 64 + d];
            ak += orfk[f * 64 + e] * Wk[e * 64 + d];
        }
        g_Mq[c] = norm * aq;
        g_Mk[c] = norm * ak;
    }
    if (tid < 64) {
        float aq = 0.f, ak = 0.f;
        for (int e = 0; e < 64; e++) {
            aq += orfq[tid * 64 + e] * bq[e];
            ak += orfk[tid * 64 + e] * bk[e];
        }
        g_cbq[tid] = norm * aq;
        g_cbk[tid] = norm * ak;
    }
}

// ---------------- K1: feature GEMMs  qf = relu(q@Mq^T + cbq)+1e-3, kf likewise, vp = v@Wv^T + bv
// rows: 16384 token-head rows (contiguous 64-float rows of the input).
// output layout permuted to [bh][s][f] for the scan stages.
__global__ void feature_kernel(const float* __restrict__ inq, const float* __restrict__ ink,
                               const float* __restrict__ inv, const float* __restrict__ Wv,
                               const float* __restrict__ bv) {
    __shared__ float A_s[64 * 64];
    __shared__ float Bt_s[64 * 64];   // [k=d][n=f]
    __shared__ float bias_s[64];
    int tid = threadIdx.x;
    int stream = blockIdx.y;          // 0=q 1=k 2=v
    int r0 = blockIdx.x * 64;
    const float* A    = (stream == 0) ? inq  : (stream == 1) ? ink  : inv;
    const float* W    = (stream == 0) ? g_Mq : (stream == 1) ? g_Mk : Wv;
    const float* bias = (stream == 0) ? g_cbq: (stream == 1) ? g_cbk: bv;
    // A tile: 64 contiguous rows
    {
        const float4* Ag = (const float4*)(A + (size_t)r0 * 64);
        float4* As4 = (float4*)A_s;
        for (int i = tid; i < 64 * 16; i += 256) As4[i] = Ag[i];
    }
    // W transposed into Bt_s[d][f]
    {
        int f = tid >> 2, db = (tid & 3) * 16;
        for (int j = 0; j < 16; j += 4) {
            float4 w = *(const float4*)(W + f * 64 + db + j);
            Bt_s[(db + j + 0) * 64 + f] = w.x;
            Bt_s[(db + j + 1) * 64 + f] = w.y;
            Bt_s[(db + j + 2) * 64 + f] = w.z;
            Bt_s[(db + j + 3) * 64 + f] = w.w;
        }
    }
    if (tid < 64) bias_s[tid] = bias[tid];
    __syncthreads();

    int rt = tid >> 4, ct = tid & 15;
    float acc[4][4] = {};
#pragma unroll
    for (int k = 0; k < 64; k += 4)
        micro4<64, 64>(A_s, Bt_s, 4 * rt, 4 * ct, k, acc);

    float* outp = (stream == 0) ? g_qf : (stream == 1) ? g_kf : g_vp;
#pragma unroll
    for (int i = 0; i < 4; i++) {
        int r = r0 + 4 * rt + i;
        int b = r >> 13, s = (r >> 3) & 1023, h = r & 7;
        float4 v;
        v.x = acc[i][0] + bias_s[4 * ct + 0];
        v.y = acc[i][1] + bias_s[4 * ct + 1];
        v.z = acc[i][2] + bias_s[4 * ct + 2];
        v.w = acc[i][3] + bias_s[4 * ct + 3];
        if (stream < 2) {
            v.x = fmaxf(v.x, 0.f) + 0.001f;
            v.y = fmaxf(v.y, 0.f) + 0.001f;
            v.z = fmaxf(v.z, 0.f) + 0.001f;
            v.w = fmaxf(v.w, 0.f) + 0.001f;
        }
        *(float4*)&outp[(((size_t)(b * HEADS + h) * SEQ + s) * 64) + 4 * ct] = v;
    }
}

// ---------------- K2: per-chunk partials  pS[f][d] = sum_u kf[u][f]*vp[u][d],  pK[f] = sum_u kf[u][f]
__global__ void chunk_partial_kernel() {
    __shared__ float kfB[64 * 64];   // [f][u]
    __shared__ float vp_s[64 * 64];  // [u][d]
    int bh = blockIdx.x, c = blockIdx.y, tid = threadIdx.x;
    const float* kf = g_kf + ((size_t)bh * SEQ + c * 64) * 64;
    const float* vp = g_vp + ((size_t)bh * SEQ + c * 64) * 64;
    for (int i = tid; i < 1024; i += 256)
        ((float4*)vp_s)[i] = ((const float4*)vp)[i];
    {
        int u = tid >> 2, fb = (tid & 3) * 16;
        for (int j = 0; j < 16; j += 4) {
            float4 w = *(const float4*)(kf + u * 64 + fb + j);
            kfB[(fb + j + 0) * 64 + u] = w.x;
            kfB[(fb + j + 1) * 64 + u] = w.y;
            kfB[(fb + j + 2) * 64 + u] = w.z;
            kfB[(fb + j + 3) * 64 + u] = w.w;
        }
    }
    __syncthreads();
    int rt = tid >> 4, ct = tid & 15;
    float acc[4][4] = {};
#pragma unroll
    for (int k = 0; k < 64; k += 4)
        micro4<64, 64>(kfB, vp_s, 4 * rt, 4 * ct, k, acc);
    float* outp = g_pS + ((size_t)bh * NCH + c) * (NF * DEP);
#pragma unroll
    for (int i = 0; i < 4; i++)
        *(float4*)&outp[(4 * rt + i) * 64 + 4 * ct] = *(float4*)acc[i];
    if (tid < 64) {  // pK[f] via coalesced global reads
        float s = 0.f;
        for (int u = 0; u < 64; u++) s += kf[u * 64 + tid];
        g_pK[((size_t)bh * NCH + c) * 64 + tid] = s;
    }
}

// ---------------- K2c: exclusive prefix over chunks for S and K
__global__ void prefix_kernel() {
    int bh = blockIdx.x, tid = threadIdx.x;
    float acc[16];
#pragma unroll
    for (int i = 0; i < 16; i++) acc[i] = 0.f;
    for (int c = 0; c < NCH; c++) {
        const float* p = g_pS + ((size_t)bh * NCH + c) * (NF * DEP);
        float* q = g_preS + ((size_t)bh * NCH + c) * (NF * DEP);
#pragma unroll
        for (int i = 0; i < 16; i++) {
            int idx = tid + i * 256;
            q[idx] = acc[i];
            acc[i] += p[idx];
        }
    }
    if (tid < 64) {
        float a = 0.f;
        for (int c = 0; c < NCH; c++) {
            g_preK[((size_t)bh * NCH + c) * 64 + tid] = a;
            a += g_pK[((size_t)bh * NCH + c) * 64 + tid];
        }
    }
}

// ---------------- K2b: qt = qf / Kc (inclusive cumsum), in place
__global__ void qt_kernel() {
    int bh = blockIdx.x, c = blockIdx.y, f = threadIdx.x;  // 64 threads
    float kc = g_preK[((size_t)bh * NCH + c) * 64 + f];
    float* qf = g_qf + ((size_t)bh * SEQ + c * 64) * 64;
    const float* kf = g_kf + ((size_t)bh * SEQ + c * 64) * 64;
    for (int u = 0; u < 64; u++) {
        kc += kf[u * 64 + f];
        qf[u * 64 + f] = qf[u * 64 + f] / kc;
    }
}

// ---------------- K3: out = qt @ S_pre + tril(qt @ kf^T) @ vp  (three 64^3 GEMMs per chunk)
__global__ void chunk_out_kernel() {
    __shared__ float qt_s[64 * 64];  // [t][f]
    __shared__ float X_s[64 * 64];   // pre[f][d] -> kfB[f][u] -> scores[t][u]
    __shared__ float Y_s[64 * 64];   // vp[u][d]
    int bh = blockIdx.x, c = blockIdx.y, tid = threadIdx.x;
    const float* qt  = g_qf  + ((size_t)bh * SEQ + c * 64) * 64;
    const float* kf  = g_kf  + ((size_t)bh * SEQ + c * 64) * 64;
    const float* vp  = g_vp  + ((size_t)bh * SEQ + c * 64) * 64;
    const float* pre = g_preS + ((size_t)bh * NCH + c) * (NF * DEP);
    for (int i = tid; i < 1024; i += 256) {
        ((float4*)qt_s)[i] = ((const float4*)qt)[i];
        ((float4*)X_s)[i]  = ((const float4*)pre)[i];
        ((float4*)Y_s)[i]  = ((const float4*)vp)[i];
    }
    __syncthreads();

    int rt = tid >> 4, ct = tid & 15;
    // GEMM3: acc = qt @ pre
    float acc[4][4] = {};
#pragma unroll
    for (int k = 0; k < 64; k += 4)
        micro4<64, 64>(qt_s, X_s, 4 * rt, 4 * ct, k, acc);
    __syncthreads();  // done reading pre

    // reload X_s as kf transposed [f][u]
    {
        int u = tid >> 2, fb = (tid & 3) * 16;
        for (int j = 0; j < 16; j += 4) {
            float4 w = *(const float4*)(kf + u * 64 + fb + j);
            X_s[(fb + j + 0) * 64 + u] = w.x;
            X_s[(fb + j + 1) * 64 + u] = w.y;
            X_s[(fb + j + 2) * 64 + u] = w.z;
            X_s[(fb + j + 3) * 64 + u] = w.w;
        }
    }
    __syncthreads();

    // GEMM1: scores[t][u] = qt @ kf^T, masked to u <= t
    float acc1[4][4] = {};
#pragma unroll
    for (int k = 0; k < 64; k += 4)
        micro4<64, 64>(qt_s, X_s, 4 * rt, 4 * ct, k, acc1);
#pragma unroll
    for (int i = 0; i < 4; i++)
#pragma unroll
        for (int j = 0; j < 4; j++)
            if (4 * ct + j > 4 * rt + i) acc1[i][j] = 0.f;
    __syncthreads();  // done reading kfB

    // write masked scores into X_s[t][u]
#pragma unroll
    for (int i = 0; i < 4; i++)
        *(float4*)&X_s[(4 * rt + i) * 64 + 4 * ct] = *(float4*)acc1[i];
    __syncthreads();

    // GEMM2: acc += scores @ vp
#pragma unroll
    for (int k = 0; k < 64; k += 4)
        micro4<64, 64>(X_s, Y_s, 4 * rt, 4 * ct, k, acc);

    // store to [b][s][h*64+d]
    int b = bh >> 3, h = bh & 7;
#pragma unroll
    for (int i = 0; i < 4; i++) {
        int s = c * 64 + 4 * rt + i;
        *(float4*)&g_attn[((size_t)b * SEQ + s) * DMODEL + h * 64 + 4 * ct] = *(float4*)acc[i];
    }
}

// ---------------- K4: final projection  out = attn @ Wfc^T + bfc   (2048 x 512 x 512)
__global__ void fc_kernel(const float* __restrict__ Wfc, const float* __restrict__ bfc,
                          float* __restrict__ out) {
    __shared__ float A_s[64 * 32];
    __shared__ float Bt_s[32 * 64];   // [e][o]
    int tid = threadIdx.x;
    int r0 = blockIdx.x * 64, o0 = blockIdx.y * 64;
    int rt = tid >> 4, ct = tid & 15;
    float acc[4][4] = {};
    for (int kt = 0; kt < DMODEL; kt += 32) {
        for (int i = tid; i < 512; i += 256) {
            int r = i >> 3, kk = (i & 7) * 4;
            *(float4*)&A_s[r * 32 + kk] = *(const float4*)&g_attn[((size_t)(r0 + r)) * DMODEL + kt + kk];
        }
        for (int i = tid; i < 512; i += 256) {
            int o = i >> 3, ee = (i & 7) * 4;
            float4 w = *(const float4*)&Wfc[((size_t)(o0 + o)) * DMODEL + kt + ee];
            Bt_s[(ee + 0) * 64 + o] = w.x;
            Bt_s[(ee + 1) * 64 + o] = w.y;
            Bt_s[(ee + 2) * 64 + o] = w.z;
            Bt_s[(ee + 3) * 64 + o] = w.w;
        }
        __syncthreads();
#pragma unroll
        for (int k = 0; k < 32; k += 4)
            micro4<32, 64>(A_s, Bt_s, 4 * rt, 4 * ct, k, acc);
        __syncthreads();
    }
#pragma unroll
    for (int i = 0; i < 4; i++) {
        int r = r0 + 4 * rt + i;
        float4 v;
        v.x = acc[i][0] + bfc[o0 + 4 * ct + 0];
        v.y = acc[i][1] + bfc[o0 + 4 * ct + 1];
        v.z = acc[i][2] + bfc[o0 + 4 * ct + 2];
        v.w = acc[i][3] + bfc[o0 + 4 * ct + 3];
        *(float4*)&out[(size_t)r * DMODEL + o0 + 4 * ct] = v;
    }
}

// ---------------- launch ----------------
extern "C" void kernel_launch(void* const* d_in, const int* in_sizes, int n_in,
                              void* d_out, int out_size) {
    (void)in_sizes; (void)n_in; (void)out_size;
    const float* q    = (const float*)d_in[0];
    const float* k    = (const float*)d_in[1];
    const float* v    = (const float*)d_in[2];
    const float* Wq   = (const float*)d_in[3];
    const float* bq   = (const float*)d_in[4];
    const float* Wk   = (const float*)d_in[5];
    const float* bk   = (const float*)d_in[6];
    const float* Wv   = (const float*)d_in[7];
    const float* bv   = (const float*)d_in[8];
    const float* orfq = (const float*)d_in[9];
    const float* orfk = (const float*)d_in[10];
    const float* Wfc  = (const float*)d_in[11];
    const float* bfc  = (const float*)d_in[12];
    float* out = (float*)d_out;

    prep_kernel<<<1, 256>>>(Wq, bq, Wk, bk, orfq, orfk);
    feature_kernel<<<dim3(NROWS / 64, 3), 256>>>(q, k, v, Wv, bv);
    chunk_partial_kernel<<<dim3(BH, NCH), 256>>>();
    prefix_kernel<<<BH, 256>>>();
    qt_kernel<<<dim3(BH, NCH), 64>>>();
    chunk_out_kernel<<<dim3(BH, NCH), 256>>>();
    fc_kernel<<<dim3(2048 / 64, DMODEL / 64), 256>>>(Wfc, bfc, out);
}

// round 3
// speedup vs baseline: 1.0665x; 1.0665x over previous
#include <cuda_runtime.h>

#define BATCH   2
#define SEQ     1024
#define HEADS   8
#define DEP     64
#define NF      64
#define BH      (BATCH*HEADS)   // 16
#define DMODEL  512
#define CHUNK   64
#define NCH     (SEQ/CHUNK)     // 16
#define NROWS   (BATCH*SEQ*HEADS) // 16384 token-head rows

typedef unsigned long long u64;

// ---------------- scratch (static device globals; no allocation) ----------------
__device__ float g_Mq[NF*DEP];
__device__ float g_Mk[NF*DEP];
__device__ float g_cbq[NF];
__device__ float g_cbk[NF];
__device__ float g_qf[BH*SEQ*NF];            // q features [bh][s][f]
__device__ float g_kf[BH*SEQ*NF];            // k features [bh][s][f]
__device__ float g_vp[BH*SEQ*DEP];           // v projected [bh][s][d]
__device__ float g_pS[BH*NCH*NF*DEP];        // per-chunk sum of kf ⊗ vp
__device__ float g_pK[BH*NCH*NF];            // per-chunk sum of kf
__device__ float g_attn[BATCH*SEQ*DMODEL];   // attention out, [b][s][h*64+d]

// ---------------- packed f32x2 helpers (sm_103a FFMA2) ----------------
__device__ __forceinline__ u64 pk2(float x) {
    u64 r; asm("mov.b64 %0, {%1,%1};" : "=l"(r) : "f"(x)); return r;
}
__device__ __forceinline__ u64 pk2b(float x, float y) {
    u64 r; asm("mov.b64 %0, {%1,%2};" : "=l"(r) : "f"(x), "f"(y)); return r;
}
__device__ __forceinline__ void fma2(u64& d, u64 a, u64 b) {
    asm("fma.rn.f32x2 %0, %1, %2, %0;" : "+l"(d) : "l"(a), "l"(b));
}
__device__ __forceinline__ float2 upk(u64 v) {
    float2 f; asm("mov.b64 {%0,%1}, %2;" : "=f"(f.x), "=f"(f.y) : "l"(v)); return f;
}

// ---------------- 4x4 (2 packed pairs) fp32x2 micro-kernel ----------------
// acc[i][p] (cols cb+2p, cb+2p+1) += sum_kk A[(rb+i)*LDA+k+kk] * B[(k+kk)*LDB+cb..]
template<int LDA, int LDB>
__device__ __forceinline__ void micro4p(const float* As, const float* Bs,
                                        int rb, int cb, int k, u64 acc[4][2]) {
    float a[4][4];
#pragma unroll
    for (int i = 0; i < 4; i++)
        *(float4*)a[i] = *(const float4*)&As[(rb + i) * LDA + k];
    u64 b[4][2];
#pragma unroll
    for (int kk = 0; kk < 4; kk++)
        *(ulonglong2*)b[kk] = *(const ulonglong2*)&Bs[(k + kk) * LDB + cb];
#pragma unroll
    for (int kk = 0; kk < 4; kk++)
#pragma unroll
        for (int i = 0; i < 4; i++) {
            u64 ad = pk2(a[i][kk]);
            fma2(acc[i][0], ad, b[kk][0]);
            fma2(acc[i][1], ad, b[kk][1]);
        }
}

// ---------------- 4x8 (4 packed pairs) micro-kernel for the fc GEMM ----------------
template<int LDA, int LDB>
__device__ __forceinline__ void micro48p(const float* As, const float* Bs,
                                         int rb, int cb, int k, u64 acc[4][4]) {
    float a[4][4];
#pragma unroll
    for (int i = 0; i < 4; i++)
        *(float4*)a[i] = *(const float4*)&As[(rb + i) * LDA + k];
#pragma unroll
    for (int kk = 0; kk < 4; kk++) {
        u64 b[4];
        *(ulonglong2*)&b[0] = *(const ulonglong2*)&Bs[(k + kk) * LDB + cb];
        *(ulonglong2*)&b[2] = *(const ulonglong2*)&Bs[(k + kk) * LDB + cb + 4];
#pragma unroll
        for (int i = 0; i < 4; i++) {
            u64 ad = pk2(a[i][kk]);
            fma2(acc[i][0], ad, b[0]);
            fma2(acc[i][1], ad, b[1]);
            fma2(acc[i][2], ad, b[2]);
            fma2(acc[i][3], ad, b[3]);
        }
    }
}

// ---------------- K0: fold Linear + ORF into one 64x64 matrix per stream ----------------
__global__ void prep_kernel(const float* __restrict__ Wq, const float* __restrict__ bq,
                            const float* __restrict__ Wk, const float* __restrict__ bk,
                            const float* __restrict__ orfq, const float* __restrict__ orfk) {
    const float norm = 0.35355339059327379f;  // 64^(-0.25)
    int tid = threadIdx.x;  // 256 threads
    for (int c = tid * 16; c < tid * 16 + 16; c++) {
        int f = c >> 6, d = c & 63;
        float aq = 0.f, ak = 0.f;
        for (int e = 0; e < 64; e++) {
            aq += orfq[f * 64 + e] * Wq[e * 64 + d];
            ak += orfk[f * 64 + e] * Wk[e * 64 + d];
        }
        g_Mq[c] = norm * aq;
        g_Mk[c] = norm * ak;
    }
    if (tid < 64) {
        float aq = 0.f, ak = 0.f;
        for (int e = 0; e < 64; e++) {
            aq += orfq[tid * 64 + e] * bq[e];
            ak += orfk[tid * 64 + e] * bk[e];
        }
        g_cbq[tid] = norm * aq;
        g_cbk[tid] = norm * ak;
    }
}

// ---------------- K1: feature GEMMs ----------------
__global__ void feature_kernel(const float* __restrict__ inq, const float* __restrict__ ink,
                               const float* __restrict__ inv, const float* __restrict__ Wv,
                               const float* __restrict__ bv) {
    __shared__ float A_s[64 * 64];
    __shared__ float Bt_s[64 * 64];   // [k=d][n=f]
    __shared__ float bias_s[64];
    int tid = threadIdx.x;
    int stream = blockIdx.y;          // 0=q 1=k 2=v
    int r0 = blockIdx.x * 64;
    const float* A    = (stream == 0) ? inq  : (stream == 1) ? ink  : inv;
    const float* W    = (stream == 0) ? g_Mq : (stream == 1) ? g_Mk : Wv;
    const float* bias = (stream == 0) ? g_cbq: (stream == 1) ? g_cbk: bv;
    {
        const float4* Ag = (const float4*)(A + (size_t)r0 * 64);
        float4* As4 = (float4*)A_s;
        for (int i = tid; i < 64 * 16; i += 256) As4[i] = Ag[i];
    }
    {
        int f = tid >> 2, db = (tid & 3) * 16;
        for (int j = 0; j < 16; j += 4) {
            float4 w = *(const float4*)(W + f * 64 + db + j);
            Bt_s[(db + j + 0) * 64 + f] = w.x;
            Bt_s[(db + j + 1) * 64 + f] = w.y;
            Bt_s[(db + j + 2) * 64 + f] = w.z;
            Bt_s[(db + j + 3) * 64 + f] = w.w;
        }
    }
    if (tid < 64) bias_s[tid] = bias[tid];
    __syncthreads();

    int rt = tid >> 4, ct = tid & 15;
    u64 acc[4][2];
    {   // init accumulators with bias (same for all rows)
        u64 b0 = pk2b(bias_s[4 * ct + 0], bias_s[4 * ct + 1]);
        u64 b1 = pk2b(bias_s[4 * ct + 2], bias_s[4 * ct + 3]);
#pragma unroll
        for (int i = 0; i < 4; i++) { acc[i][0] = b0; acc[i][1] = b1; }
    }
#pragma unroll
    for (int k = 0; k < 64; k += 4)
        micro4p<64, 64>(A_s, Bt_s, 4 * rt, 4 * ct, k, acc);

    float* outp = (stream == 0) ? g_qf : (stream == 1) ? g_kf : g_vp;
#pragma unroll
    for (int i = 0; i < 4; i++) {
        int r = r0 + 4 * rt + i;
        int b = r >> 13, s = (r >> 3) & 1023, h = r & 7;
        float2 p0 = upk(acc[i][0]), p1 = upk(acc[i][1]);
        float4 v = make_float4(p0.x, p0.y, p1.x, p1.y);
        if (stream < 2) {
            v.x = fmaxf(v.x, 0.f) + 0.001f;
            v.y = fmaxf(v.y, 0.f) + 0.001f;
            v.z = fmaxf(v.z, 0.f) + 0.001f;
            v.w = fmaxf(v.w, 0.f) + 0.001f;
        }
        *(float4*)&outp[(((size_t)(b * HEADS + h) * SEQ + s) * 64) + 4 * ct] = v;
    }
}

// ---------------- K2: per-chunk partials  pS[f][d] = sum_u kf[u][f]*vp[u][d],  pK[f] = sum_u kf[u][f]
__global__ void chunk_partial_kernel() {
    __shared__ float kfB[64 * 64];   // [f][u]
    __shared__ float vp_s[64 * 64];  // [u][d]
    __shared__ float pk_s[256];
    int bh = blockIdx.x, c = blockIdx.y, tid = threadIdx.x;
    const float* kf = g_kf + ((size_t)bh * SEQ + c * 64) * 64;
    const float* vp = g_vp + ((size_t)bh * SEQ + c * 64) * 64;
    for (int i = tid; i < 1024; i += 256)
        ((float4*)vp_s)[i] = ((const float4*)vp)[i];
    {
        int u = tid >> 2, fb = (tid & 3) * 16;
        for (int j = 0; j < 16; j += 4) {
            float4 w = *(const float4*)(kf + u * 64 + fb + j);
            kfB[(fb + j + 0) * 64 + u] = w.x;
            kfB[(fb + j + 1) * 64 + u] = w.y;
            kfB[(fb + j + 2) * 64 + u] = w.z;
            kfB[(fb + j + 3) * 64 + u] = w.w;
        }
    }
    {   // parallel pK partials (coalesced global reads, L2-hot)
        int f = tid & 63, qtr = tid >> 6;
        float ps = 0.f;
        for (int u = qtr * 16; u < qtr * 16 + 16; u++) ps += kf[u * 64 + f];
        pk_s[qtr * 64 + f] = ps;
    }
    __syncthreads();
    if (tid < 64)
        g_pK[((size_t)bh * NCH + c) * 64 + tid] =
            pk_s[tid] + pk_s[64 + tid] + pk_s[128 + tid] + pk_s[192 + tid];

    int rt = tid >> 4, ct = tid & 15;
    u64 acc[4][2] = {};
#pragma unroll
    for (int k = 0; k < 64; k += 4)
        micro4p<64, 64>(kfB, vp_s, 4 * rt, 4 * ct, k, acc);
    float* outp = g_pS + ((size_t)bh * NCH + c) * (NF * DEP);
#pragma unroll
    for (int i = 0; i < 4; i++) {
        float2 p0 = upk(acc[i][0]), p1 = upk(acc[i][1]);
        *(float4*)&outp[(4 * rt + i) * 64 + 4 * ct] = make_float4(p0.x, p0.y, p1.x, p1.y);
    }
}

// ---------------- K3 (fused): prefix + qt + chunk output ----------------
// out = qt @ preS + tril(qt @ kf^T) @ vp, where qt = qf / cumsum(kf) and
// preS/preK are rebuilt per block from per-chunk partials (L2-resident).
__global__ void chunk_out_fused() {
    __shared__ float qt_s[4096];   // qf -> qt in place
    __shared__ float kT_s[4096];   // scratch -> kf^T [f][u] -> vp [u][d]
    __shared__ float S_s[4096];    // preS [f][d] -> masked scores [t][u]
    int bh = blockIdx.x, c = blockIdx.y, tid = threadIdx.x;
    const float* qf_g = g_qf + ((size_t)bh * SEQ + c * 64) * 64;
    const float* kf_g = g_kf + ((size_t)bh * SEQ + c * 64) * 64;
    const float* vp_g = g_vp + ((size_t)bh * SEQ + c * 64) * 64;

    // load qf
    for (int i = tid; i < 1024; i += 256)
        ((float4*)qt_s)[i] = ((const float4*)qf_g)[i];

    // within-chunk cumsum of kf, quarter-split: thread = (f, quarter)
    int f = tid & 63, qtr = tid >> 6;
    {
        float ps = 0.f;
        for (int u = qtr * 16; u < qtr * 16 + 16; u++) ps += kf_g[u * 64 + f];
        kT_s[qtr * 64 + f] = ps;                    // scratch: quarter sums
    }
    if (qtr == 0) {                                  // preK base from prior chunks
        float b = 0.f;
        for (int c2 = 0; c2 < c; c2++) b += g_pK[((size_t)bh * NCH + c2) * 64 + f];
        kT_s[256 + f] = b;
    }
    __syncthreads();
    {
        float kc = kT_s[256 + f];
        for (int q2 = 0; q2 < qtr; q2++) kc += kT_s[q2 * 64 + f];
        for (int u = qtr * 16; u < qtr * 16 + 16; u++) {
            kc += kf_g[u * 64 + f];
            qt_s[u * 64 + f] = __fdividef(qt_s[u * 64 + f], kc);
        }
    }
    __syncthreads();   // qt ready; scratch region free

    // transpose kf into kT_s [f][u]
    {
        int u = tid >> 2, fb = (tid & 3) * 16;
        for (int j = 0; j < 16; j += 4) {
            float4 w = *(const float4*)(kf_g + u * 64 + fb + j);
            kT_s[(fb + j + 0) * 64 + u] = w.x;
            kT_s[(fb + j + 1) * 64 + u] = w.y;
            kT_s[(fb + j + 2) * 64 + u] = w.z;
            kT_s[(fb + j + 3) * 64 + u] = w.w;
        }
    }

    int rt = tid >> 4, ct = tid & 15;
    u64 acc[4][2] = {};

    if (c > 0) {
        // rebuild preS[c] = sum_{c'<c} pS[c'] in registers, then to smem
        float4 sa[4] = {};
        const float4* pS4 = (const float4*)(g_pS + (size_t)bh * NCH * 4096);
        for (int c2 = 0; c2 < c; c2++) {
            const float4* t = pS4 + (size_t)c2 * 1024;
#pragma unroll
            for (int p = 0; p < 4; p++) {
                float4 v = t[tid + p * 256];
                sa[p].x += v.x; sa[p].y += v.y; sa[p].z += v.z; sa[p].w += v.w;
            }
        }
#pragma unroll
        for (int p = 0; p < 4; p++) ((float4*)S_s)[tid + p * 256] = sa[p];
        __syncthreads();
        // GEMM3: acc = qt @ preS
#pragma unroll
        for (int k = 0; k < 64; k += 4)
            micro4p<64, 64>(qt_s, S_s, 4 * rt, 4 * ct, k, acc);
    }
    __syncthreads();   // kT transpose visible; preS reads done

    // GEMM1: scores = qt @ kf^T
    u64 acc1[4][2] = {};
#pragma unroll
    for (int k = 0; k < 64; k += 4)
        micro4p<64, 64>(qt_s, kT_s, 4 * rt, 4 * ct, k, acc1);
    __syncthreads();   // done reading kT_s / S_s

    // masked scores -> S_s; vp -> kT_s
#pragma unroll
    for (int i = 0; i < 4; i++) {
        int r = 4 * rt + i;
        float2 p0 = upk(acc1[i][0]), p1 = upk(acc1[i][1]);
        float4 v;
        v.x = (4 * ct + 0 <= r) ? p0.x : 0.f;
        v.y = (4 * ct + 1 <= r) ? p0.y : 0.f;
        v.z = (4 * ct + 2 <= r) ? p1.x : 0.f;
        v.w = (4 * ct + 3 <= r) ? p1.y : 0.f;
        *(float4*)&S_s[r * 64 + 4 * ct] = v;
    }
    for (int i = tid; i < 1024; i += 256)
        ((float4*)kT_s)[i] = ((const float4*)vp_g)[i];
    __syncthreads();

    // GEMM2: acc += scores @ vp
#pragma unroll
    for (int k = 0; k < 64; k += 4)
        micro4p<64, 64>(S_s, kT_s, 4 * rt, 4 * ct, k, acc);

    // store to [b][s][h*64+d]
    int b = bh >> 3, h = bh & 7;
#pragma unroll
    for (int i = 0; i < 4; i++) {
        int s = c * 64 + 4 * rt + i;
        float2 p0 = upk(acc[i][0]), p1 = upk(acc[i][1]);
        *(float4*)&g_attn[((size_t)b * SEQ + s) * DMODEL + h * 64 + 4 * ct] =
            make_float4(p0.x, p0.y, p1.x, p1.y);
    }
}

// ---------------- K4: out = attn @ Wfc^T + bfc  (2048 x 512 x 512), 64x128 tiles
__global__ void fc_kernel(const float* __restrict__ Wfc, const float* __restrict__ bfc,
                          float* __restrict__ out) {
    __shared__ float A_s[64 * 32];
    __shared__ float Bt_s[32 * 128];   // [e][o]
    int tid = threadIdx.x;
    int r0 = blockIdx.x * 64, o0 = blockIdx.y * 128;
    int rt = tid >> 4, ct = tid & 15;
    u64 acc[4][4];
    {
        u64 b0 = pk2b(bfc[o0 + 8 * ct + 0], bfc[o0 + 8 * ct + 1]);
        u64 b1 = pk2b(bfc[o0 + 8 * ct + 2], bfc[o0 + 8 * ct + 3]);
        u64 b2 = pk2b(bfc[o0 + 8 * ct + 4], bfc[o0 + 8 * ct + 5]);
        u64 b3 = pk2b(bfc[o0 + 8 * ct + 6], bfc[o0 + 8 * ct + 7]);
#pragma unroll
        for (int i = 0; i < 4; i++) {
            acc[i][0] = b0; acc[i][1] = b1; acc[i][2] = b2; acc[i][3] = b3;
        }
    }
    for (int kt = 0; kt < DMODEL; kt += 32) {
        for (int i = tid; i < 512; i += 256) {
            int r = i >> 3, kk = (i & 7) * 4;
            *(float4*)&A_s[r * 32 + kk] =
                *(const float4*)&g_attn[(size_t)(r0 + r) * DMODEL + kt + kk];
        }
        for (int i = tid; i < 1024; i += 256) {
            int o = i >> 3, ee = (i & 7) * 4;
            float4 w = *(const float4*)&Wfc[(size_t)(o0 + o) * DMODEL + kt + ee];
            Bt_s[(ee + 0) * 128 + o] = w.x;
            Bt_s[(ee + 1) * 128 + o] = w.y;
            Bt_s[(ee + 2) * 128 + o] = w.z;
            Bt_s[(ee + 3) * 128 + o] = w.w;
        }
        __syncthreads();
#pragma unroll
        for (int k = 0; k < 32; k += 4)
            micro48p<32, 128>(A_s, Bt_s, 4 * rt, 8 * ct, k, acc);
        __syncthreads();
    }
#pragma unroll
    for (int i = 0; i < 4; i++) {
        int r = r0 + 4 * rt + i;
        float2 p0 = upk(acc[i][0]), p1 = upk(acc[i][1]);
        float2 p2 = upk(acc[i][2]), p3 = upk(acc[i][3]);
        *(float4*)&out[(size_t)r * DMODEL + o0 + 8 * ct]     = make_float4(p0.x, p0.y, p1.x, p1.y);
        *(float4*)&out[(size_t)r * DMODEL + o0 + 8 * ct + 4] = make_float4(p2.x, p2.y, p3.x, p3.y);
    }
}

// ---------------- launch ----------------
extern "C" void kernel_launch(void* const* d_in, const int* in_sizes, int n_in,
                              void* d_out, int out_size) {
    (void)in_sizes; (void)n_in; (void)out_size;
    const float* q    = (const float*)d_in[0];
    const float* k    = (const float*)d_in[1];
    const float* v    = (const float*)d_in[2];
    const float* Wq   = (const float*)d_in[3];
    const float* bq   = (const float*)d_in[4];
    const float* Wk   = (const float*)d_in[5];
    const float* bk   = (const float*)d_in[6];
    const float* Wv   = (const float*)d_in[7];
    const float* bv   = (const float*)d_in[8];
    const float* orfq = (const float*)d_in[9];
    const float* orfk = (const float*)d_in[10];
    const float* Wfc  = (const float*)d_in[11];
    const float* bfc  = (const float*)d_in[12];
    float* out = (float*)d_out;

    prep_kernel<<<1, 256>>>(Wq, bq, Wk, bk, orfq, orfk);
    feature_kernel<<<dim3(NROWS / 64, 3), 256>>>(q, k, v, Wv, bv);
    chunk_partial_kernel<<<dim3(BH, NCH), 256>>>();
    chunk_out_fused<<<dim3(BH, NCH), 256>>>();
    fc_kernel<<<dim3(2048 / 64, DMODEL / 128), 256>>>(Wfc, bfc, out);
}

// round 4
// speedup vs baseline: 1.9028x; 1.7842x over previous
#include <cuda_runtime.h>

#define BATCH   2
#define SEQ     1024
#define HEADS   8
#define DEP     64
#define NF      64
#define BH      (BATCH*HEADS)   // 16
#define DMODEL  512
#define CHUNK   64
#define NCH     (SEQ/CHUNK)     // 16
#define NROWS   (BATCH*SEQ*HEADS) // 16384 token-head rows

typedef unsigned long long u64;

// ---------------- scratch (static device globals; no allocation) ----------------
__device__ float g_Mq[NF*DEP];
__device__ float g_Mk[NF*DEP];
__device__ float g_cbq[NF];
__device__ float g_cbk[NF];
__device__ float g_qf[BH*SEQ*NF];            // q features [bh][s][f]
__device__ float g_kf[BH*SEQ*NF];            // k features [bh][s][f]
__device__ float g_vp[BH*SEQ*DEP];           // v projected [bh][s][d]
__device__ float g_pS[BH*NCH*NF*DEP];        // per-chunk sum of kf ⊗ vp
__device__ float g_pK[BH*NCH*NF];            // per-chunk sum of kf
__device__ float g_attn[BATCH*SEQ*DMODEL];   // attention out, [b][s][h*64+d]

// ---------------- packed f32x2 helpers (sm_103a FFMA2) ----------------
__device__ __forceinline__ u64 pk2(float x) {
    u64 r; asm("mov.b64 %0, {%1,%1};" : "=l"(r) : "f"(x)); return r;
}
__device__ __forceinline__ u64 pk2b(float x, float y) {
    u64 r; asm("mov.b64 %0, {%1,%2};" : "=l"(r) : "f"(x), "f"(y)); return r;
}
__device__ __forceinline__ void fma2(u64& d, u64 a, u64 b) {
    asm("fma.rn.f32x2 %0, %1, %2, %0;" : "+l"(d) : "l"(a), "l"(b));
}
__device__ __forceinline__ float2 upk(u64 v) {
    float2 f; asm("mov.b64 {%0,%1}, %2;" : "=f"(f.x), "=f"(f.y) : "l"(v)); return f;
}

// ---------------- 4x4 (2 packed pairs) fp32x2 micro-kernel ----------------
template<int LDA, int LDB>
__device__ __forceinline__ void micro4p(const float* As, const float* Bs,
                                        int rb, int cb, int k, u64 acc[4][2]) {
    float a[4][4];
#pragma unroll
    for (int i = 0; i < 4; i++)
        *(float4*)a[i] = *(const float4*)&As[(rb + i) * LDA + k];
    u64 b[4][2];
#pragma unroll
    for (int kk = 0; kk < 4; kk++)
        *(ulonglong2*)b[kk] = *(const ulonglong2*)&Bs[(k + kk) * LDB + cb];
#pragma unroll
    for (int kk = 0; kk < 4; kk++)
#pragma unroll
        for (int i = 0; i < 4; i++) {
            u64 ad = pk2(a[i][kk]);
            fma2(acc[i][0], ad, b[kk][0]);
            fma2(acc[i][1], ad, b[kk][1]);
        }
}

// ---------------- 4x8 (4 packed pairs) micro-kernel for the fc GEMM ----------------
template<int LDA, int LDB>
__device__ __forceinline__ void micro48p(const float* As, const float* Bs,
                                         int rb, int cb, int k, u64 acc[4][4]) {
    float a[4][4];
#pragma unroll
    for (int i = 0; i < 4; i++)
        *(float4*)a[i] = *(const float4*)&As[(rb + i) * LDA + k];
#pragma unroll
    for (int kk = 0; kk < 4; kk++) {
        u64 b[4];
        *(ulonglong2*)&b[0] = *(const ulonglong2*)&Bs[(k + kk) * LDB + cb];
        *(ulonglong2*)&b[2] = *(const ulonglong2*)&Bs[(k + kk) * LDB + cb + 4];
#pragma unroll
        for (int i = 0; i < 4; i++) {
            u64 ad = pk2(a[i][kk]);
            fma2(acc[i][0], ad, b[0]);
            fma2(acc[i][1], ad, b[1]);
            fma2(acc[i][2], ad, b[2]);
            fma2(acc[i][3], ad, b[3]);
        }
    }
}

// ---------------- K0: fold Linear + ORF into one 64x64 matrix per stream ----------------
// M[f][d] = norm * sum_e orf[f][e] * W[e][d];  cb[f] = norm * sum_e orf[f][e] * b[e]
// 2 blocks (q-stream, k-stream), smem-staged GEMM — was the single-block,
// global-load-bound hotspot (~100us on one SM).
__global__ void prep_kernel(const float* __restrict__ Wq, const float* __restrict__ bq,
                            const float* __restrict__ Wk, const float* __restrict__ bk,
                            const float* __restrict__ orfq, const float* __restrict__ orfk) {
    __shared__ float orf_s[4096];   // [f][e]
    __shared__ float W_s[4096];     // [e][d]  (already [k][n] layout)
    __shared__ float b_s[64];
    const float norm = 0.35355339059327379f;  // 64^(-0.25)
    int s = blockIdx.x, tid = threadIdx.x;
    const float* orf = s ? orfk : orfq;
    const float* W   = s ? Wk   : Wq;
    const float* bb  = s ? bk   : bq;
    float* M  = s ? g_Mk  : g_Mq;
    float* cb = s ? g_cbk : g_cbq;
    for (int i = tid; i < 1024; i += 256) {
        ((float4*)orf_s)[i] = ((const float4*)orf)[i];
        ((float4*)W_s)[i]   = ((const float4*)W)[i];
    }
    if (tid < 64) b_s[tid] = bb[tid];
    __syncthreads();

    int rt = tid >> 4, ct = tid & 15;
    u64 acc[4][2] = {};
#pragma unroll
    for (int k = 0; k < 64; k += 4)
        micro4p<64, 64>(orf_s, W_s, 4 * rt, 4 * ct, k, acc);
#pragma unroll
    for (int i = 0; i < 4; i++) {
        float2 p0 = upk(acc[i][0]), p1 = upk(acc[i][1]);
        *(float4*)&M[(4 * rt + i) * 64 + 4 * ct] =
            make_float4(norm * p0.x, norm * p0.y, norm * p1.x, norm * p1.y);
    }
    if (tid < 64) {
        float a = 0.f;
#pragma unroll
        for (int e = 0; e < 64; e++) a += orf_s[tid * 64 + e] * b_s[e];
        cb[tid] = norm * a;
    }
}

// ---------------- K1: feature GEMMs ----------------
__global__ void feature_kernel(const float* __restrict__ inq, const float* __restrict__ ink,
                               const float* __restrict__ inv, const float* __restrict__ Wv,
                               const float* __restrict__ bv) {
    __shared__ float A_s[64 * 64];
    __shared__ float Bt_s[64 * 64];   // [k=d][n=f]
    __shared__ float bias_s[64];
    int tid = threadIdx.x;
    int stream = blockIdx.y;          // 0=q 1=k 2=v
    int r0 = blockIdx.x * 64;
    const float* A    = (stream == 0) ? inq  : (stream == 1) ? ink  : inv;
    const float* W    = (stream == 0) ? g_Mq : (stream == 1) ? g_Mk : Wv;
    const float* bias = (stream == 0) ? g_cbq: (stream == 1) ? g_cbk: bv;
    {
        const float4* Ag = (const float4*)(A + (size_t)r0 * 64);
        float4* As4 = (float4*)A_s;
        for (int i = tid; i < 64 * 16; i += 256) As4[i] = Ag[i];
    }
    {
        int f = tid >> 2, db = (tid & 3) * 16;
        for (int j = 0; j < 16; j += 4) {
            float4 w = *(const float4*)(W + f * 64 + db + j);
            Bt_s[(db + j + 0) * 64 + f] = w.x;
            Bt_s[(db + j + 1) * 64 + f] = w.y;
            Bt_s[(db + j + 2) * 64 + f] = w.z;
            Bt_s[(db + j + 3) * 64 + f] = w.w;
        }
    }
    if (tid < 64) bias_s[tid] = bias[tid];
    __syncthreads();

    int rt = tid >> 4, ct = tid & 15;
    u64 acc[4][2];
    {   // init accumulators with bias
        u64 b0 = pk2b(bias_s[4 * ct + 0], bias_s[4 * ct + 1]);
        u64 b1 = pk2b(bias_s[4 * ct + 2], bias_s[4 * ct + 3]);
#pragma unroll
        for (int i = 0; i < 4; i++) { acc[i][0] = b0; acc[i][1] = b1; }
    }
#pragma unroll
    for (int k = 0; k < 64; k += 4)
        micro4p<64, 64>(A_s, Bt_s, 4 * rt, 4 * ct, k, acc);

    float* outp = (stream == 0) ? g_qf : (stream == 1) ? g_kf : g_vp;
#pragma unroll
    for (int i = 0; i < 4; i++) {
        int r = r0 + 4 * rt + i;
        int b = r >> 13, s = (r >> 3) & 1023, h = r & 7;
        float2 p0 = upk(acc[i][0]), p1 = upk(acc[i][1]);
        float4 v = make_float4(p0.x, p0.y, p1.x, p1.y);
        if (stream < 2) {
            v.x = fmaxf(v.x, 0.f) + 0.001f;
            v.y = fmaxf(v.y, 0.f) + 0.001f;
            v.z = fmaxf(v.z, 0.f) + 0.001f;
            v.w = fmaxf(v.w, 0.f) + 0.001f;
        }
        *(float4*)&outp[(((size_t)(b * HEADS + h) * SEQ + s) * 64) + 4 * ct] = v;
    }
}

// ---------------- K2: per-chunk partials ----------------
__global__ void chunk_partial_kernel() {
    __shared__ float kfB[64 * 64];   // [f][u]
    __shared__ float vp_s[64 * 64];  // [u][d]
    __shared__ float pk_s[256];
    int bh = blockIdx.x, c = blockIdx.y, tid = threadIdx.x;
    const float* kf = g_kf + ((size_t)bh * SEQ + c * 64) * 64;
    const float* vp = g_vp + ((size_t)bh * SEQ + c * 64) * 64;
    for (int i = tid; i < 1024; i += 256)
        ((float4*)vp_s)[i] = ((const float4*)vp)[i];
    {
        int u = tid >> 2, fb = (tid & 3) * 16;
        for (int j = 0; j < 16; j += 4) {
            float4 w = *(const float4*)(kf + u * 64 + fb + j);
            kfB[(fb + j + 0) * 64 + u] = w.x;
            kfB[(fb + j + 1) * 64 + u] = w.y;
            kfB[(fb + j + 2) * 64 + u] = w.z;
            kfB[(fb + j + 3) * 64 + u] = w.w;
        }
    }
    {   // parallel pK partials
        int f = tid & 63, qtr = tid >> 6;
        float ps = 0.f;
        for (int u = qtr * 16; u < qtr * 16 + 16; u++) ps += kf[u * 64 + f];
        pk_s[qtr * 64 + f] = ps;
    }
    __syncthreads();
    if (tid < 64)
        g_pK[((size_t)bh * NCH + c) * 64 + tid] =
            pk_s[tid] + pk_s[64 + tid] + pk_s[128 + tid] + pk_s[192 + tid];

    int rt = tid >> 4, ct = tid & 15;
    u64 acc[4][2] = {};
#pragma unroll
    for (int k = 0; k < 64; k += 4)
        micro4p<64, 64>(kfB, vp_s, 4 * rt, 4 * ct, k, acc);
    float* outp = g_pS + ((size_t)bh * NCH + c) * (NF * DEP);
#pragma unroll
    for (int i = 0; i < 4; i++) {
        float2 p0 = upk(acc[i][0]), p1 = upk(acc[i][1]);
        *(float4*)&outp[(4 * rt + i) * 64 + 4 * ct] = make_float4(p0.x, p0.y, p1.x, p1.y);
    }
}

// ---------------- K3 (fused): prefix + qt + chunk output ----------------
__global__ void chunk_out_fused() {
    __shared__ float qt_s[4096];   // qf -> qt in place
    __shared__ float kT_s[4096];   // scratch -> kf^T [f][u] -> vp [u][d]
    __shared__ float S_s[4096];    // preS [f][d] -> masked scores [t][u]
    int bh = blockIdx.x, c = blockIdx.y, tid = threadIdx.x;
    const float* qf_g = g_qf + ((size_t)bh * SEQ + c * 64) * 64;
    const float* kf_g = g_kf + ((size_t)bh * SEQ + c * 64) * 64;
    const float* vp_g = g_vp + ((size_t)bh * SEQ + c * 64) * 64;

    for (int i = tid; i < 1024; i += 256)
        ((float4*)qt_s)[i] = ((const float4*)qf_g)[i];

    // within-chunk cumsum of kf, quarter-split
    int f = tid & 63, qtr = tid >> 6;
    {
        float ps = 0.f;
        for (int u = qtr * 16; u < qtr * 16 + 16; u++) ps += kf_g[u * 64 + f];
        kT_s[qtr * 64 + f] = ps;
    }
    if (qtr == 0) {   // preK base from prior chunks
        float b = 0.f;
        for (int c2 = 0; c2 < c; c2++) b += g_pK[((size_t)bh * NCH + c2) * 64 + f];
        kT_s[256 + f] = b;
    }
    __syncthreads();
    {
        float kc = kT_s[256 + f];
        for (int q2 = 0; q2 < qtr; q2++) kc += kT_s[q2 * 64 + f];
        for (int u = qtr * 16; u < qtr * 16 + 16; u++) {
            kc += kf_g[u * 64 + f];
            qt_s[u * 64 + f] = __fdividef(qt_s[u * 64 + f], kc);
        }
    }
    __syncthreads();

    // transpose kf into kT_s [f][u]
    {
        int u = tid >> 2, fb = (tid & 3) * 16;
        for (int j = 0; j < 16; j += 4) {
            float4 w = *(const float4*)(kf_g + u * 64 + fb + j);
            kT_s[(fb + j + 0) * 64 + u] = w.x;
            kT_s[(fb + j + 1) * 64 + u] = w.y;
            kT_s[(fb + j + 2) * 64 + u] = w.z;
            kT_s[(fb + j + 3) * 64 + u] = w.w;
        }
    }

    int rt = tid >> 4, ct = tid & 15;
    u64 acc[4][2] = {};

    if (c > 0) {
        float4 sa[4] = {};
        const float4* pS4 = (const float4*)(g_pS + (size_t)bh * NCH * 4096);
        for (int c2 = 0; c2 < c; c2++) {
            const float4* t = pS4 + (size_t)c2 * 1024;
#pragma unroll
            for (int p = 0; p < 4; p++) {
                float4 v = t[tid + p * 256];
                sa[p].x += v.x; sa[p].y += v.y; sa[p].z += v.z; sa[p].w += v.w;
            }
        }
#pragma unroll
        for (int p = 0; p < 4; p++) ((float4*)S_s)[tid + p * 256] = sa[p];
        __syncthreads();
#pragma unroll
        for (int k = 0; k < 64; k += 4)
            micro4p<64, 64>(qt_s, S_s, 4 * rt, 4 * ct, k, acc);
    }
    __syncthreads();

    // GEMM1: scores = qt @ kf^T
    u64 acc1[4][2] = {};
#pragma unroll
    for (int k = 0; k < 64; k += 4)
        micro4p<64, 64>(qt_s, kT_s, 4 * rt, 4 * ct, k, acc1);
    __syncthreads();

    // masked scores -> S_s; vp -> kT_s
#pragma unroll
    for (int i = 0; i < 4; i++) {
        int r = 4 * rt + i;
        float2 p0 = upk(acc1[i][0]), p1 = upk(acc1[i][1]);
        float4 v;
        v.x = (4 * ct + 0 <= r) ? p0.x : 0.f;
        v.y = (4 * ct + 1 <= r) ? p0.y : 0.f;
        v.z = (4 * ct + 2 <= r) ? p1.x : 0.f;
        v.w = (4 * ct + 3 <= r) ? p1.y : 0.f;
        *(float4*)&S_s[r * 64 + 4 * ct] = v;
    }
    for (int i = tid; i < 1024; i += 256)
        ((float4*)kT_s)[i] = ((const float4*)vp_g)[i];
    __syncthreads();

#pragma unroll
    for (int k = 0; k < 64; k += 4)
        micro4p<64, 64>(S_s, kT_s, 4 * rt, 4 * ct, k, acc);

    int b = bh >> 3, h = bh & 7;
#pragma unroll
    for (int i = 0; i < 4; i++) {
        int s = c * 64 + 4 * rt + i;
        float2 p0 = upk(acc[i][0]), p1 = upk(acc[i][1]);
        *(float4*)&g_attn[((size_t)b * SEQ + s) * DMODEL + h * 64 + 4 * ct] =
            make_float4(p0.x, p0.y, p1.x, p1.y);
    }
}

// ---------------- K4: out = attn @ Wfc^T + bfc  (2048 x 512 x 512), 64x128 tiles
__global__ void fc_kernel(const float* __restrict__ Wfc, const float* __restrict__ bfc,
                          float* __restrict__ out) {
    __shared__ float A_s[64 * 32];
    __shared__ float Bt_s[32 * 128];   // [e][o]
    int tid = threadIdx.x;
    int r0 = blockIdx.x * 64, o0 = blockIdx.y * 128;
    int rt = tid >> 4, ct = tid & 15;
    u64 acc[4][4];
    {
        u64 b0 = pk2b(bfc[o0 + 8 * ct + 0], bfc[o0 + 8 * ct + 1]);
        u64 b1 = pk2b(bfc[o0 + 8 * ct + 2], bfc[o0 + 8 * ct + 3]);
        u64 b2 = pk2b(bfc[o0 + 8 * ct + 4], bfc[o0 + 8 * ct + 5]);
        u64 b3 = pk2b(bfc[o0 + 8 * ct + 6], bfc[o0 + 8 * ct + 7]);
#pragma unroll
        for (int i = 0; i < 4; i++) {
            acc[i][0] = b0; acc[i][1] = b1; acc[i][2] = b2; acc[i][3] = b3;
        }
    }
    for (int kt = 0; kt < DMODEL; kt += 32) {
        for (int i = tid; i < 512; i += 256) {
            int r = i >> 3, kk = (i & 7) * 4;
            *(float4*)&A_s[r * 32 + kk] =
                *(const float4*)&g_attn[(size_t)(r0 + r) * DMODEL + kt + kk];
        }
        for (int i = tid; i < 1024; i += 256) {
            int o = i >> 3, ee = (i & 7) * 4;
            float4 w = *(const float4*)&Wfc[(size_t)(o0 + o) * DMODEL + kt + ee];
            Bt_s[(ee + 0) * 128 + o] = w.x;
            Bt_s[(ee + 1) * 128 + o] = w.y;
            Bt_s[(ee + 2) * 128 + o] = w.z;
            Bt_s[(ee + 3) * 128 + o] = w.w;
        }
        __syncthreads();
#pragma unroll
        for (int k = 0; k < 32; k += 4)
            micro48p<32, 128>(A_s, Bt_s, 4 * rt, 8 * ct, k, acc);
        __syncthreads();
    }
#pragma unroll
    for (int i = 0; i < 4; i++) {
        int r = r0 + 4 * rt + i;
        float2 p0 = upk(acc[i][0]), p1 = upk(acc[i][1]);
        float2 p2 = upk(acc[i][2]), p3 = upk(acc[i][3]);
        *(float4*)&out[(size_t)r * DMODEL + o0 + 8 * ct]     = make_float4(p0.x, p0.y, p1.x, p1.y);
        *(float4*)&out[(size_t)r * DMODEL + o0 + 8 * ct + 4] = make_float4(p2.x, p2.y, p3.x, p3.y);
    }
}

// ---------------- launch ----------------
extern "C" void kernel_launch(void* const* d_in, const int* in_sizes, int n_in,
                              void* d_out, int out_size) {
    (void)in_sizes; (void)n_in; (void)out_size;
    const float* q    = (const float*)d_in[0];
    const float* k    = (const float*)d_in[1];
    const float* v    = (const float*)d_in[2];
    const float* Wq   = (const float*)d_in[3];
    const float* bq   = (const float*)d_in[4];
    const float* Wk   = (const float*)d_in[5];
    const float* bk   = (const float*)d_in[6];
    const float* Wv   = (const float*)d_in[7];
    const float* bv   = (const float*)d_in[8];
    const float* orfq = (const float*)d_in[9];
    const float* orfk = (const float*)d_in[10];
    const float* Wfc  = (const float*)d_in[11];
    const float* bfc  = (const float*)d_in[12];
    float* out = (float*)d_out;

    prep_kernel<<<2, 256>>>(Wq, bq, Wk, bk, orfq, orfk);
    feature_kernel<<<dim3(NROWS / 64, 3), 256>>>(q, k, v, Wv, bv);
    chunk_partial_kernel<<<dim3(BH, NCH), 256>>>();
    chunk_out_fused<<<dim3(BH, NCH), 256>>>();
    fc_kernel<<<dim3(2048 / 64, DMODEL / 128), 256>>>(Wfc, bfc, out);
}

// round 5
// speedup vs baseline: 2.2183x; 1.1658x over previous
#include <cuda_runtime.h>

#define BATCH   2
#define SEQ     1024
#define HEADS   8
#define DEP     64
#define NF      64
#define BH      (BATCH*HEADS)   // 16
#define DMODEL  512
#define CHUNK   64
#define NCH     (SEQ/CHUNK)     // 16
#define NROWS   (BATCH*SEQ*HEADS) // 16384 token-head rows

typedef unsigned long long u64;

// ---------------- scratch (static device globals; no allocation) ----------------
__device__ float g_Mq[NF*DEP];
__device__ float g_Mk[NF*DEP];
__device__ float g_cbq[NF];
__device__ float g_cbk[NF];
__device__ float g_qf[BH*SEQ*NF];            // q features [bh][s][f]
__device__ float g_kf[BH*SEQ*NF];            // k features [bh][s][f]
__device__ float g_vp[BH*SEQ*DEP];           // v projected [bh][s][d]
__device__ float g_pS[BH*NCH*NF*DEP];        // per-chunk sum of kf ⊗ vp
__device__ float g_preS[BH*NCH*NF*DEP];      // exclusive prefix of pS
__device__ float g_pK[BH*NCH*NF];            // per-chunk sum of kf
__device__ float g_preK[BH*NCH*NF];          // exclusive prefix of pK
__device__ float g_attn[BATCH*SEQ*DMODEL];   // attention out, [b][s][h*64+d]
__device__ float g_fcp[2][BATCH*SEQ*DMODEL]; // split-k partials for fc

// ---------------- packed f32x2 helpers (sm_103a FFMA2) ----------------
__device__ __forceinline__ u64 pk2(float x) {
    u64 r; asm("mov.b64 %0, {%1,%1};" : "=l"(r) : "f"(x)); return r;
}
__device__ __forceinline__ u64 pk2b(float x, float y) {
    u64 r; asm("mov.b64 %0, {%1,%2};" : "=l"(r) : "f"(x), "f"(y)); return r;
}
__device__ __forceinline__ void fma2(u64& d, u64 a, u64 b) {
    asm("fma.rn.f32x2 %0, %1, %2, %0;" : "+l"(d) : "l"(a), "l"(b));
}
__device__ __forceinline__ float2 upk(u64 v) {
    float2 f; asm("mov.b64 {%0,%1}, %2;" : "=f"(f.x), "=f"(f.y) : "l"(v)); return f;
}

// ---------------- 4x4 micro-kernel (2 packed pairs wide) ----------------
template<int LDA, int LDB>
__device__ __forceinline__ void micro4p(const float* As, const float* Bs,
                                        int rb, int cb, int k, u64 acc[4][2]) {
    float a[4][4];
#pragma unroll
    for (int i = 0; i < 4; i++)
        *(float4*)a[i] = *(const float4*)&As[(rb + i) * LDA + k];
    u64 b[4][2];
#pragma unroll
    for (int kk = 0; kk < 4; kk++)
        *(ulonglong2*)b[kk] = *(const ulonglong2*)&Bs[(k + kk) * LDB + cb];
#pragma unroll
    for (int kk = 0; kk < 4; kk++)
#pragma unroll
        for (int i = 0; i < 4; i++) {
            u64 ad = pk2(a[i][kk]);
            fma2(acc[i][0], ad, b[kk][0]);
            fma2(acc[i][1], ad, b[kk][1]);
        }
}

// ---------------- 8x4 micro-kernel (feature): 1.5 B/MAC ----------------
template<int LDA, int LDB>
__device__ __forceinline__ void micro84p(const float* As, const float* Bs,
                                         int rb, int cb, int k, u64 acc[8][2]) {
    float a[8][4];
#pragma unroll
    for (int i = 0; i < 8; i++)
        *(float4*)a[i] = *(const float4*)&As[(rb + i) * LDA + k];
#pragma unroll
    for (int kk = 0; kk < 4; kk++) {
        u64 b[2];
        *(ulonglong2*)b = *(const ulonglong2*)&Bs[(k + kk) * LDB + cb];
#pragma unroll
        for (int i = 0; i < 8; i++) {
            u64 ad = pk2(a[i][kk]);
            fma2(acc[i][0], ad, b[0]);
            fma2(acc[i][1], ad, b[1]);
        }
    }
}

// ---------------- 8x8 micro-kernel (fc): 1.0 B/MAC ----------------
template<int LDA, int LDB>
__device__ __forceinline__ void micro88p(const float* As, const float* Bs,
                                         int rb, int cb, int k, u64 acc[8][4]) {
    float a[8][4];
#pragma unroll
    for (int i = 0; i < 8; i++)
        *(float4*)a[i] = *(const float4*)&As[(rb + i) * LDA + k];
#pragma unroll
    for (int kk = 0; kk < 4; kk++) {
        u64 b[4];
        *(ulonglong2*)&b[0] = *(const ulonglong2*)&Bs[(k + kk) * LDB + cb];
        *(ulonglong2*)&b[2] = *(const ulonglong2*)&Bs[(k + kk) * LDB + cb + 4];
#pragma unroll
        for (int i = 0; i < 8; i++) {
            u64 ad = pk2(a[i][kk]);
            fma2(acc[i][0], ad, b[0]);
            fma2(acc[i][1], ad, b[1]);
            fma2(acc[i][2], ad, b[2]);
            fma2(acc[i][3], ad, b[3]);
        }
    }
}

// ---------------- K0: fold Linear + ORF (2 blocks) ----------------
__global__ void prep_kernel(const float* __restrict__ Wq, const float* __restrict__ bq,
                            const float* __restrict__ Wk, const float* __restrict__ bk,
                            const float* __restrict__ orfq, const float* __restrict__ orfk) {
    __shared__ float orf_s[4096];   // [f][e]
    __shared__ float W_s[4096];     // [e][d]
    __shared__ float b_s[64];
    const float norm = 0.35355339059327379f;  // 64^(-0.25)
    int s = blockIdx.x, tid = threadIdx.x;
    const float* orf = s ? orfk : orfq;
    const float* W   = s ? Wk   : Wq;
    const float* bb  = s ? bk   : bq;
    float* M  = s ? g_Mk  : g_Mq;
    float* cb = s ? g_cbk : g_cbq;
    for (int i = tid; i < 1024; i += 256) {
        ((float4*)orf_s)[i] = ((const float4*)orf)[i];
        ((float4*)W_s)[i]   = ((const float4*)W)[i];
    }
    if (tid < 64) b_s[tid] = bb[tid];
    __syncthreads();

    int rt = tid >> 4, ct = tid & 15;
    u64 acc[4][2] = {};
#pragma unroll
    for (int k = 0; k < 64; k += 4)
        micro4p<64, 64>(orf_s, W_s, 4 * rt, 4 * ct, k, acc);
#pragma unroll
    for (int i = 0; i < 4; i++) {
        float2 p0 = upk(acc[i][0]), p1 = upk(acc[i][1]);
        *(float4*)&M[(4 * rt + i) * 64 + 4 * ct] =
            make_float4(norm * p0.x, norm * p0.y, norm * p1.x, norm * p1.y);
    }
    if (tid < 64) {
        float a = 0.f;
#pragma unroll
        for (int e = 0; e < 64; e++) a += orf_s[tid * 64 + e] * b_s[e];
        cb[tid] = norm * a;
    }
}

// ---------------- K1: feature GEMMs, 128-row tiles, 8x4/thread ----------------
__global__ void feature_kernel(const float* __restrict__ inq, const float* __restrict__ ink,
                               const float* __restrict__ inv, const float* __restrict__ Wv,
                               const float* __restrict__ bv) {
    __shared__ float A_s[128 * 64];
    __shared__ float Bt_s[64 * 64];   // [k=d][n=f]
    __shared__ float bias_s[64];
    int tid = threadIdx.x;
    int stream = blockIdx.y;          // 0=q 1=k 2=v
    int r0 = blockIdx.x * 128;
    const float* A    = (stream == 0) ? inq  : (stream == 1) ? ink  : inv;
    const float* W    = (stream == 0) ? g_Mq : (stream == 1) ? g_Mk : Wv;
    const float* bias = (stream == 0) ? g_cbq: (stream == 1) ? g_cbk: bv;
    {
        const float4* Ag = (const float4*)(A + (size_t)r0 * 64);
        float4* As4 = (float4*)A_s;
        for (int i = tid; i < 128 * 16; i += 256) As4[i] = Ag[i];
    }
    {
        int f = tid >> 2, db = (tid & 3) * 16;
        for (int j = 0; j < 16; j += 4) {
            float4 w = *(const float4*)(W + f * 64 + db + j);
            Bt_s[(db + j + 0) * 64 + f] = w.x;
            Bt_s[(db + j + 1) * 64 + f] = w.y;
            Bt_s[(db + j + 2) * 64 + f] = w.z;
            Bt_s[(db + j + 3) * 64 + f] = w.w;
        }
    }
    if (tid < 64) bias_s[tid] = bias[tid];
    __syncthreads();

    int rt = tid >> 4, ct = tid & 15;     // 16 row-groups x 16 col-groups
    u64 acc[8][2];
    {
        u64 b0 = pk2b(bias_s[4 * ct + 0], bias_s[4 * ct + 1]);
        u64 b1 = pk2b(bias_s[4 * ct + 2], bias_s[4 * ct + 3]);
#pragma unroll
        for (int i = 0; i < 8; i++) { acc[i][0] = b0; acc[i][1] = b1; }
    }
#pragma unroll
    for (int k = 0; k < 64; k += 4)
        micro84p<64, 64>(A_s, Bt_s, 8 * rt, 4 * ct, k, acc);

    float* outp = (stream == 0) ? g_qf : (stream == 1) ? g_kf : g_vp;
#pragma unroll
    for (int i = 0; i < 8; i++) {
        int r = r0 + 8 * rt + i;
        int b = r >> 13, s = (r >> 3) & 1023, h = r & 7;
        float2 p0 = upk(acc[i][0]), p1 = upk(acc[i][1]);
        float4 v = make_float4(p0.x, p0.y, p1.x, p1.y);
        if (stream < 2) {
            v.x = fmaxf(v.x, 0.f) + 0.001f;
            v.y = fmaxf(v.y, 0.f) + 0.001f;
            v.z = fmaxf(v.z, 0.f) + 0.001f;
            v.w = fmaxf(v.w, 0.f) + 0.001f;
        }
        *(float4*)&outp[(((size_t)(b * HEADS + h) * SEQ + s) * 64) + 4 * ct] = v;
    }
}

// ---------------- K2: per-chunk partials ----------------
__global__ void chunk_partial_kernel() {
    __shared__ float kfB[64 * 64];   // [f][u]
    __shared__ float vp_s[64 * 64];  // [u][d]
    __shared__ float pk_s[256];
    int bh = blockIdx.x, c = blockIdx.y, tid = threadIdx.x;
    const float* kf = g_kf + ((size_t)bh * SEQ + c * 64) * 64;
    const float* vp = g_vp + ((size_t)bh * SEQ + c * 64) * 64;
    for (int i = tid; i < 1024; i += 256)
        ((float4*)vp_s)[i] = ((const float4*)vp)[i];
    {
        int u = tid >> 2, fb = (tid & 3) * 16;
        for (int j = 0; j < 16; j += 4) {
            float4 w = *(const float4*)(kf + u * 64 + fb + j);
            kfB[(fb + j + 0) * 64 + u] = w.x;
            kfB[(fb + j + 1) * 64 + u] = w.y;
            kfB[(fb + j + 2) * 64 + u] = w.z;
            kfB[(fb + j + 3) * 64 + u] = w.w;
        }
    }
    {
        int f = tid & 63, qtr = tid >> 6;
        float ps = 0.f;
        for (int u = qtr * 16; u < qtr * 16 + 16; u++) ps += kf[u * 64 + f];
        pk_s[qtr * 64 + f] = ps;
    }
    __syncthreads();
    if (tid < 64)
        g_pK[((size_t)bh * NCH + c) * 64 + tid] =
            pk_s[tid] + pk_s[64 + tid] + pk_s[128 + tid] + pk_s[192 + tid];

    int rt = tid >> 4, ct = tid & 15;
    u64 acc[4][2] = {};
#pragma unroll
    for (int k = 0; k < 64; k += 4)
        micro4p<64, 64>(kfB, vp_s, 4 * rt, 4 * ct, k, acc);
    float* outp = g_pS + ((size_t)bh * NCH + c) * (NF * DEP);
#pragma unroll
    for (int i = 0; i < 4; i++) {
        float2 p0 = upk(acc[i][0]), p1 = upk(acc[i][1]);
        *(float4*)&outp[(4 * rt + i) * 64 + 4 * ct] = make_float4(p0.x, p0.y, p1.x, p1.y);
    }
}

// ---------------- K2c: parallel exclusive prefix over chunks (element-parallel) ----------------
__global__ void prefix_kernel() {
    int blk = blockIdx.x;        // 256 blocks = bh*16 + seg
    int bh = blk >> 4, seg = blk & 15, tid = threadIdx.x;
    int e = seg * 256 + tid;     // element within the 4096-float tile
    const float* src = g_pS   + (size_t)bh * NCH * 4096;
    float*       dst = g_preS + (size_t)bh * NCH * 4096;
    float acc = 0.f;
#pragma unroll
    for (int c = 0; c < NCH; c++) {
        dst[c * 4096 + e] = acc;
        acc += src[c * 4096 + e];
    }
    if (seg == 0 && tid < 64) {
        float a = 0.f;
        for (int c = 0; c < NCH; c++) {
            g_preK[((size_t)bh * NCH + c) * 64 + tid] = a;
            a += g_pK[((size_t)bh * NCH + c) * 64 + tid];
        }
    }
}

// ---------------- K3: qt + chunk output (preS/preK loaded directly) ----------------
__global__ void chunk_out_fused() {
    __shared__ float qt_s[4096];   // qf -> qt in place
    __shared__ float kT_s[4096];   // scratch -> kf^T [f][u] -> vp [u][d]
    __shared__ float S_s[4096];    // preS [f][d] -> masked scores [t][u]
    int bh = blockIdx.x, c = blockIdx.y, tid = threadIdx.x;
    const float* qf_g = g_qf + ((size_t)bh * SEQ + c * 64) * 64;
    const float* kf_g = g_kf + ((size_t)bh * SEQ + c * 64) * 64;
    const float* vp_g = g_vp + ((size_t)bh * SEQ + c * 64) * 64;

    for (int i = tid; i < 1024; i += 256)
        ((float4*)qt_s)[i] = ((const float4*)qf_g)[i];

    // within-chunk cumsum of kf, quarter-split
    int f = tid & 63, qtr = tid >> 6;
    {
        float ps = 0.f;
        for (int u = qtr * 16; u < qtr * 16 + 16; u++) ps += kf_g[u * 64 + f];
        kT_s[qtr * 64 + f] = ps;
    }
    __syncthreads();
    {
        float kc = g_preK[((size_t)bh * NCH + c) * 64 + f];
        for (int q2 = 0; q2 < qtr; q2++) kc += kT_s[q2 * 64 + f];
        for (int u = qtr * 16; u < qtr * 16 + 16; u++) {
            kc += kf_g[u * 64 + f];
            qt_s[u * 64 + f] = __fdividef(qt_s[u * 64 + f], kc);
        }
    }
    __syncthreads();

    // transpose kf into kT_s [f][u]
    {
        int u = tid >> 2, fb = (tid & 3) * 16;
        for (int j = 0; j < 16; j += 4) {
            float4 w = *(const float4*)(kf_g + u * 64 + fb + j);
            kT_s[(fb + j + 0) * 64 + u] = w.x;
            kT_s[(fb + j + 1) * 64 + u] = w.y;
            kT_s[(fb + j + 2) * 64 + u] = w.z;
            kT_s[(fb + j + 3) * 64 + u] = w.w;
        }
    }

    int rt = tid >> 4, ct = tid & 15;
    u64 acc[4][2] = {};

    if (c > 0) {
        const float4* pre4 = (const float4*)(g_preS + ((size_t)bh * NCH + c) * 4096);
        for (int i = tid; i < 1024; i += 256) ((float4*)S_s)[i] = pre4[i];
        __syncthreads();
#pragma unroll
        for (int k = 0; k < 64; k += 4)
            micro4p<64, 64>(qt_s, S_s, 4 * rt, 4 * ct, k, acc);
    }
    __syncthreads();

    // GEMM1: scores = qt @ kf^T
    u64 acc1[4][2] = {};
#pragma unroll
    for (int k = 0; k < 64; k += 4)
        micro4p<64, 64>(qt_s, kT_s, 4 * rt, 4 * ct, k, acc1);
    __syncthreads();

    // masked scores -> S_s; vp -> kT_s
#pragma unroll
    for (int i = 0; i < 4; i++) {
        int r = 4 * rt + i;
        float2 p0 = upk(acc1[i][0]), p1 = upk(acc1[i][1]);
        float4 v;
        v.x = (4 * ct + 0 <= r) ? p0.x : 0.f;
        v.y = (4 * ct + 1 <= r) ? p0.y : 0.f;
        v.z = (4 * ct + 2 <= r) ? p1.x : 0.f;
        v.w = (4 * ct + 3 <= r) ? p1.y : 0.f;
        *(float4*)&S_s[r * 64 + 4 * ct] = v;
    }
    for (int i = tid; i < 1024; i += 256)
        ((float4*)kT_s)[i] = ((const float4*)vp_g)[i];
    __syncthreads();

#pragma unroll
    for (int k = 0; k < 64; k += 4)
        micro4p<64, 64>(S_s, kT_s, 4 * rt, 4 * ct, k, acc);

    int b = bh >> 3, h = bh & 7;
#pragma unroll
    for (int i = 0; i < 4; i++) {
        int s = c * 64 + 4 * rt + i;
        float2 p0 = upk(acc[i][0]), p1 = upk(acc[i][1]);
        *(float4*)&g_attn[((size_t)b * SEQ + s) * DMODEL + h * 64 + 4 * ct] =
            make_float4(p0.x, p0.y, p1.x, p1.y);
    }
}

// ---------------- K4a: fc split-k partial GEMM, 128x128 tiles, 8x8/thread ----------------
__global__ void __launch_bounds__(256) fc_split_kernel(const float* __restrict__ Wfc) {
    __shared__ float A_s[128 * 16];
    __shared__ float Bt_s[16 * 128];   // [e][o]
    int tid = threadIdx.x;
    int r0 = blockIdx.x * 128, o0 = blockIdx.y * 128;
    int kbase = blockIdx.z * 256;
    int rt = tid >> 4, ct = tid & 15;
    u64 acc[8][4] = {};
    for (int kp = 0; kp < 256; kp += 16) {
        for (int i = tid; i < 512; i += 256) {
            int r = i >> 2, kk4 = (i & 3) * 4;
            *(float4*)&A_s[r * 16 + kk4] =
                *(const float4*)&g_attn[(size_t)(r0 + r) * DMODEL + kbase + kp + kk4];
        }
        for (int i = tid; i < 512; i += 256) {
            int o = i >> 2, ee4 = (i & 3) * 4;
            float4 w = *(const float4*)&Wfc[(size_t)(o0 + o) * DMODEL + kbase + kp + ee4];
            Bt_s[(ee4 + 0) * 128 + o] = w.x;
            Bt_s[(ee4 + 1) * 128 + o] = w.y;
            Bt_s[(ee4 + 2) * 128 + o] = w.z;
            Bt_s[(ee4 + 3) * 128 + o] = w.w;
        }
        __syncthreads();
#pragma unroll
        for (int k = 0; k < 16; k += 4)
            micro88p<16, 128>(A_s, Bt_s, 8 * rt, 8 * ct, k, acc);
        __syncthreads();
    }
    float* outp = g_fcp[blockIdx.z];
#pragma unroll
    for (int i = 0; i < 8; i++) {
        int r = r0 + 8 * rt + i;
        float2 p0 = upk(acc[i][0]), p1 = upk(acc[i][1]);
        float2 p2 = upk(acc[i][2]), p3 = upk(acc[i][3]);
        *(float4*)&outp[(size_t)r * DMODEL + o0 + 8 * ct]     = make_float4(p0.x, p0.y, p1.x, p1.y);
        *(float4*)&outp[(size_t)r * DMODEL + o0 + 8 * ct + 4] = make_float4(p2.x, p2.y, p3.x, p3.y);
    }
}

// ---------------- K4b: reduce split-k partials + bias ----------------
__global__ void fc_reduce_kernel(const float* __restrict__ bfc, float* __restrict__ out) {
    int idx = blockIdx.x * 512 + threadIdx.x;   // float4 index
#pragma unroll
    for (int rep = 0; rep < 2; rep++, idx += 256) {
        int o = (idx * 4) & (DMODEL - 1);
        float4 a = ((const float4*)g_fcp[0])[idx];
        float4 b = ((const float4*)g_fcp[1])[idx];
        float4 c = *(const float4*)&bfc[o];
        ((float4*)out)[idx] = make_float4(a.x + b.x + c.x, a.y + b.y + c.y,
                                          a.z + b.z + c.z, a.w + b.w + c.w);
    }
}

// ---------------- launch ----------------
extern "C" void kernel_launch(void* const* d_in, const int* in_sizes, int n_in,
                              void* d_out, int out_size) {
    (void)in_sizes; (void)n_in; (void)out_size;
    const float* q    = (const float*)d_in[0];
    const float* k    = (const float*)d_in[1];
    const float* v    = (const float*)d_in[2];
    const float* Wq   = (const float*)d_in[3];
    const float* bq   = (const float*)d_in[4];
    const float* Wk   = (const float*)d_in[5];
    const float* bk   = (const float*)d_in[6];
    const float* Wv   = (const float*)d_in[7];
    const float* bv   = (const float*)d_in[8];
    const float* orfq = (const float*)d_in[9];
    const float* orfk = (const float*)d_in[10];
    const float* Wfc  = (const float*)d_in[11];
    const float* bfc  = (const float*)d_in[12];
    float* out = (float*)d_out;

    prep_kernel<<<2, 256>>>(Wq, bq, Wk, bk, orfq, orfk);
    feature_kernel<<<dim3(NROWS / 128, 3), 256>>>(q, k, v, Wv, bv);
    chunk_partial_kernel<<<dim3(BH, NCH), 256>>>();
    prefix_kernel<<<256, 256>>>();
    chunk_out_fused<<<dim3(BH, NCH), 256>>>();
    fc_split_kernel<<<dim3(2048 / 128, DMODEL / 128, 2), 256>>>(Wfc);
    fc_reduce_kernel<<<(BATCH * SEQ * DMODEL / 4) / 512, 256>>>(bfc, out);
}

// round 6
// speedup vs baseline: 2.3260x; 1.0486x over previous
#include <cuda_runtime.h>

#define BATCH   2
#define SEQ     1024
#define HEADS   8
#define DEP     64
#define NF      64
#define BH      (BATCH*HEADS)   // 16
#define DMODEL  512
#define CHUNK   64
#define NCH     (SEQ/CHUNK)     // 16
#define NROWS   (BATCH*SEQ*HEADS) // 16384 token-head rows

typedef unsigned long long u64;

// ---------------- scratch (static device globals; no allocation) ----------------
__device__ float g_Mq[NF*DEP];
__device__ float g_Mk[NF*DEP];
__device__ float g_cbq[NF];
__device__ float g_cbk[NF];
__device__ float g_qf[BH*SEQ*NF];            // q features [bh][s][f]
__device__ float g_kf[BH*SEQ*NF];            // k features [bh][s][f]
__device__ float g_vp[BH*SEQ*DEP];           // v projected [bh][s][d]
__device__ float g_pS[BH*NCH*NF*DEP];        // per-chunk sum of kf ⊗ vp
__device__ float g_preS[BH*NCH*NF*DEP];      // exclusive prefix of pS
__device__ float g_pK[BH*NCH*NF];            // per-chunk sum of kf
__device__ float g_preK[BH*NCH*NF];          // exclusive prefix of pK
__device__ float g_attn[BATCH*SEQ*DMODEL];   // attention out, [b][s][h*64+d]
__device__ float g_fcp[2][BATCH*SEQ*DMODEL]; // split-k partials for fc

// ---------------- packed f32x2 helpers (sm_103a FFMA2) ----------------
__device__ __forceinline__ u64 pk2(float x) {
    u64 r; asm("mov.b64 %0, {%1,%1};" : "=l"(r) : "f"(x)); return r;
}
__device__ __forceinline__ u64 pk2b(float x, float y) {
    u64 r; asm("mov.b64 %0, {%1,%2};" : "=l"(r) : "f"(x), "f"(y)); return r;
}
__device__ __forceinline__ void fma2(u64& d, u64 a, u64 b) {
    asm("fma.rn.f32x2 %0, %1, %2, %0;" : "+l"(d) : "l"(a), "l"(b));
}
__device__ __forceinline__ float2 upk(u64 v) {
    float2 f; asm("mov.b64 {%0,%1}, %2;" : "=f"(f.x), "=f"(f.y) : "l"(v)); return f;
}

// ---------------- 4x4 micro-kernel (2 packed pairs wide) ----------------
template<int LDA, int LDB>
__device__ __forceinline__ void micro4p(const float* As, const float* Bs,
                                        int rb, int cb, int k, u64 acc[4][2]) {
    float a[4][4];
#pragma unroll
    for (int i = 0; i < 4; i++)
        *(float4*)a[i] = *(const float4*)&As[(rb + i) * LDA + k];
    u64 b[4][2];
#pragma unroll
    for (int kk = 0; kk < 4; kk++)
        *(ulonglong2*)b[kk] = *(const ulonglong2*)&Bs[(k + kk) * LDB + cb];
#pragma unroll
    for (int kk = 0; kk < 4; kk++)
#pragma unroll
        for (int i = 0; i < 4; i++) {
            u64 ad = pk2(a[i][kk]);
            fma2(acc[i][0], ad, b[kk][0]);
            fma2(acc[i][1], ad, b[kk][1]);
        }
}

// ---------------- 8x4 micro-kernel (feature): 1.5 B/MAC ----------------
template<int LDA, int LDB>
__device__ __forceinline__ void micro84p(const float* As, const float* Bs,
                                         int rb, int cb, int k, u64 acc[8][2]) {
    float a[8][4];
#pragma unroll
    for (int i = 0; i < 8; i++)
        *(float4*)a[i] = *(const float4*)&As[(rb + i) * LDA + k];
#pragma unroll
    for (int kk = 0; kk < 4; kk++) {
        u64 b[2];
        *(ulonglong2*)b = *(const ulonglong2*)&Bs[(k + kk) * LDB + cb];
#pragma unroll
        for (int i = 0; i < 8; i++) {
            u64 ad = pk2(a[i][kk]);
            fma2(acc[i][0], ad, b[0]);
            fma2(acc[i][1], ad, b[1]);
        }
    }
}

// ---------------- 8x8 micro-kernel (fc): 1.0 B/MAC ----------------
template<int LDA, int LDB>
__device__ __forceinline__ void micro88p(const float* As, const float* Bs,
                                         int rb, int cb, int k, u64 acc[8][4]) {
    float a[8][4];
#pragma unroll
    for (int i = 0; i < 8; i++)
        *(float4*)a[i] = *(const float4*)&As[(rb + i) * LDA + k];
#pragma unroll
    for (int kk = 0; kk < 4; kk++) {
        u64 b[4];
        *(ulonglong2*)&b[0] = *(const ulonglong2*)&Bs[(k + kk) * LDB + cb];
        *(ulonglong2*)&b[2] = *(const ulonglong2*)&Bs[(k + kk) * LDB + cb + 4];
#pragma unroll
        for (int i = 0; i < 8; i++) {
            u64 ad = pk2(a[i][kk]);
            fma2(acc[i][0], ad, b[0]);
            fma2(acc[i][1], ad, b[1]);
            fma2(acc[i][2], ad, b[2]);
            fma2(acc[i][3], ad, b[3]);
        }
    }
}

// ---------------- K0: fold Linear + ORF (2 blocks) ----------------
__global__ void prep_kernel(const float* __restrict__ Wq, const float* __restrict__ bq,
                            const float* __restrict__ Wk, const float* __restrict__ bk,
                            const float* __restrict__ orfq, const float* __restrict__ orfk) {
    __shared__ float orf_s[4096];   // [f][e]
    __shared__ float W_s[4096];     // [e][d]
    __shared__ float b_s[64];
    const float norm = 0.35355339059327379f;  // 64^(-0.25)
    int s = blockIdx.x, tid = threadIdx.x;
    const float* orf = s ? orfk : orfq;
    const float* W   = s ? Wk   : Wq;
    const float* bb  = s ? bk   : bq;
    float* M  = s ? g_Mk  : g_Mq;
    float* cb = s ? g_cbk : g_cbq;
    for (int i = tid; i < 1024; i += 256) {
        ((float4*)orf_s)[i] = ((const float4*)orf)[i];
        ((float4*)W_s)[i]   = ((const float4*)W)[i];
    }
    if (tid < 64) b_s[tid] = bb[tid];
    __syncthreads();

    int rt = tid >> 4, ct = tid & 15;
    u64 acc[4][2] = {};
#pragma unroll
    for (int k = 0; k < 64; k += 4)
        micro4p<64, 64>(orf_s, W_s, 4 * rt, 4 * ct, k, acc);
#pragma unroll
    for (int i = 0; i < 4; i++) {
        float2 p0 = upk(acc[i][0]), p1 = upk(acc[i][1]);
        *(float4*)&M[(4 * rt + i) * 64 + 4 * ct] =
            make_float4(norm * p0.x, norm * p0.y, norm * p1.x, norm * p1.y);
    }
    if (tid < 64) {
        float a = 0.f;
#pragma unroll
        for (int e = 0; e < 64; e++) a += orf_s[tid * 64 + e] * b_s[e];
        cb[tid] = norm * a;
    }
}

// ---------------- K1: feature GEMMs, 128-row tiles, 8x4/thread ----------------
__global__ void feature_kernel(const float* __restrict__ inq, const float* __restrict__ ink,
                               const float* __restrict__ inv, const float* __restrict__ Wv,
                               const float* __restrict__ bv) {
    __shared__ float A_s[128 * 64];
    __shared__ float Bt_s[64 * 64];   // [k=d][n=f]
    __shared__ float bias_s[64];
    int tid = threadIdx.x;
    int stream = blockIdx.y;          // 0=q 1=k 2=v
    int r0 = blockIdx.x * 128;
    const float* A    = (stream == 0) ? inq  : (stream == 1) ? ink  : inv;
    const float* W    = (stream == 0) ? g_Mq : (stream == 1) ? g_Mk : Wv;
    const float* bias = (stream == 0) ? g_cbq: (stream == 1) ? g_cbk: bv;
    {
        const float4* Ag = (const float4*)(A + (size_t)r0 * 64);
        float4* As4 = (float4*)A_s;
        for (int i = tid; i < 128 * 16; i += 256) As4[i] = Ag[i];
    }
    {
        int f = tid >> 2, db = (tid & 3) * 16;
        for (int j = 0; j < 16; j += 4) {
            float4 w = *(const float4*)(W + f * 64 + db + j);
            Bt_s[(db + j + 0) * 64 + f] = w.x;
            Bt_s[(db + j + 1) * 64 + f] = w.y;
            Bt_s[(db + j + 2) * 64 + f] = w.z;
            Bt_s[(db + j + 3) * 64 + f] = w.w;
        }
    }
    if (tid < 64) bias_s[tid] = bias[tid];
    __syncthreads();

    int rt = tid >> 4, ct = tid & 15;
    u64 acc[8][2];
    {
        u64 b0 = pk2b(bias_s[4 * ct + 0], bias_s[4 * ct + 1]);
        u64 b1 = pk2b(bias_s[4 * ct + 2], bias_s[4 * ct + 3]);
#pragma unroll
        for (int i = 0; i < 8; i++) { acc[i][0] = b0; acc[i][1] = b1; }
    }
#pragma unroll
    for (int k = 0; k < 64; k += 4)
        micro84p<64, 64>(A_s, Bt_s, 8 * rt, 4 * ct, k, acc);

    float* outp = (stream == 0) ? g_qf : (stream == 1) ? g_kf : g_vp;
#pragma unroll
    for (int i = 0; i < 8; i++) {
        int r = r0 + 8 * rt + i;
        int b = r >> 13, s = (r >> 3) & 1023, h = r & 7;
        float2 p0 = upk(acc[i][0]), p1 = upk(acc[i][1]);
        float4 v = make_float4(p0.x, p0.y, p1.x, p1.y);
        if (stream < 2) {
            v.x = fmaxf(v.x, 0.f) + 0.001f;
            v.y = fmaxf(v.y, 0.f) + 0.001f;
            v.z = fmaxf(v.z, 0.f) + 0.001f;
            v.w = fmaxf(v.w, 0.f) + 0.001f;
        }
        *(float4*)&outp[(((size_t)(b * HEADS + h) * SEQ + s) * 64) + 4 * ct] = v;
    }
}

// ---------------- K2: per-chunk partials ----------------
__global__ void chunk_partial_kernel() {
    __shared__ float kfB[64 * 64];   // [f][u]
    __shared__ float vp_s[64 * 64];  // [u][d]
    __shared__ float pk_s[256];
    int bh = blockIdx.x, c = blockIdx.y, tid = threadIdx.x;
    const float* kf = g_kf + ((size_t)bh * SEQ + c * 64) * 64;
    const float* vp = g_vp + ((size_t)bh * SEQ + c * 64) * 64;
    for (int i = tid; i < 1024; i += 256)
        ((float4*)vp_s)[i] = ((const float4*)vp)[i];
    {
        int u = tid >> 2, fb = (tid & 3) * 16;
        for (int j = 0; j < 16; j += 4) {
            float4 w = *(const float4*)(kf + u * 64 + fb + j);
            kfB[(fb + j + 0) * 64 + u] = w.x;
            kfB[(fb + j + 1) * 64 + u] = w.y;
            kfB[(fb + j + 2) * 64 + u] = w.z;
            kfB[(fb + j + 3) * 64 + u] = w.w;
        }
    }
    {
        int f = tid & 63, qtr = tid >> 6;
        float ps = 0.f;
        for (int u = qtr * 16; u < qtr * 16 + 16; u++) ps += kf[u * 64 + f];
        pk_s[qtr * 64 + f] = ps;
    }
    __syncthreads();
    if (tid < 64)
        g_pK[((size_t)bh * NCH + c) * 64 + tid] =
            pk_s[tid] + pk_s[64 + tid] + pk_s[128 + tid] + pk_s[192 + tid];

    int rt = tid >> 4, ct = tid & 15;
    u64 acc[4][2] = {};
#pragma unroll
    for (int k = 0; k < 64; k += 4)
        micro4p<64, 64>(kfB, vp_s, 4 * rt, 4 * ct, k, acc);
    float* outp = g_pS + ((size_t)bh * NCH + c) * (NF * DEP);
#pragma unroll
    for (int i = 0; i < 4; i++) {
        float2 p0 = upk(acc[i][0]), p1 = upk(acc[i][1]);
        *(float4*)&outp[(4 * rt + i) * 64 + 4 * ct] = make_float4(p0.x, p0.y, p1.x, p1.y);
    }
}

// ---------------- K2c: batched-load exclusive prefix over chunks ----------------
// Each thread stages all NCH chunk values in registers first (MLP=16), scans in
// registers, then stores — removes the load->add->store serial chain that made
// the previous version latency-bound (issue=1.5%).
__global__ void prefix_kernel() {
    int blk = blockIdx.x;            // 128 blocks: bh(16) x seg(8)
    int bh = blk >> 3, seg = blk & 7, tid = threadIdx.x;
    int e2 = seg * 256 + tid;        // float2 index within the 2048-float2 tile
    const float2* src = (const float2*)(g_pS   + (size_t)bh * NCH * 4096);
    float2*       dst = (float2*)(g_preS + (size_t)bh * NCH * 4096);
    float2 v[NCH];
#pragma unroll
    for (int c = 0; c < NCH; c++) v[c] = src[c * 2048 + e2];
    float2 acc = make_float2(0.f, 0.f);
#pragma unroll
    for (int c = 0; c < NCH; c++) {
        dst[c * 2048 + e2] = acc;
        acc.x += v[c].x; acc.y += v[c].y;
    }
    if (seg == 0 && tid < 64) {
        float kv[NCH];
#pragma unroll
        for (int c = 0; c < NCH; c++) kv[c] = g_pK[((size_t)bh * NCH + c) * 64 + tid];
        float a = 0.f;
#pragma unroll
        for (int c = 0; c < NCH; c++) {
            g_preK[((size_t)bh * NCH + c) * 64 + tid] = a;
            a += kv[c];
        }
    }
}

// ---------------- K3: qt + chunk output (preS/preK loaded directly) ----------------
__global__ void chunk_out_fused() {
    __shared__ float qt_s[4096];   // qf -> qt in place
    __shared__ float kT_s[4096];   // scratch -> kf^T [f][u] -> vp [u][d]
    __shared__ float S_s[4096];    // preS [f][d] -> masked scores [t][u]
    int bh = blockIdx.x, c = blockIdx.y, tid = threadIdx.x;
    const float* qf_g = g_qf + ((size_t)bh * SEQ + c * 64) * 64;
    const float* kf_g = g_kf + ((size_t)bh * SEQ + c * 64) * 64;
    const float* vp_g = g_vp + ((size_t)bh * SEQ + c * 64) * 64;

    for (int i = tid; i < 1024; i += 256)
        ((float4*)qt_s)[i] = ((const float4*)qf_g)[i];

    // within-chunk cumsum of kf, quarter-split
    int f = tid & 63, qtr = tid >> 6;
    {
        float ps = 0.f;
        for (int u = qtr * 16; u < qtr * 16 + 16; u++) ps += kf_g[u * 64 + f];
        kT_s[qtr * 64 + f] = ps;
    }
    __syncthreads();
    {
        float kc = g_preK[((size_t)bh * NCH + c) * 64 + f];
        for (int q2 = 0; q2 < qtr; q2++) kc += kT_s[q2 * 64 + f];
        for (int u = qtr * 16; u < qtr * 16 + 16; u++) {
            kc += kf_g[u * 64 + f];
            qt_s[u * 64 + f] = __fdividef(qt_s[u * 64 + f], kc);
        }
    }
    __syncthreads();

    // transpose kf into kT_s [f][u]
    {
        int u = tid >> 2, fb = (tid & 3) * 16;
        for (int j = 0; j < 16; j += 4) {
            float4 w = *(const float4*)(kf_g + u * 64 + fb + j);
            kT_s[(fb + j + 0) * 64 + u] = w.x;
            kT_s[(fb + j + 1) * 64 + u] = w.y;
            kT_s[(fb + j + 2) * 64 + u] = w.z;
            kT_s[(fb + j + 3) * 64 + u] = w.w;
        }
    }

    int rt = tid >> 4, ct = tid & 15;
    u64 acc[4][2] = {};

    if (c > 0) {
        const float4* pre4 = (const float4*)(g_preS + ((size_t)bh * NCH + c) * 4096);
        for (int i = tid; i < 1024; i += 256) ((float4*)S_s)[i] = pre4[i];
        __syncthreads();
#pragma unroll
        for (int k = 0; k < 64; k += 4)
            micro4p<64, 64>(qt_s, S_s, 4 * rt, 4 * ct, k, acc);
    }
    __syncthreads();

    // GEMM1: scores = qt @ kf^T
    u64 acc1[4][2] = {};
#pragma unroll
    for (int k = 0; k < 64; k += 4)
        micro4p<64, 64>(qt_s, kT_s, 4 * rt, 4 * ct, k, acc1);
    __syncthreads();

    // masked scores -> S_s; vp -> kT_s
#pragma unroll
    for (int i = 0; i < 4; i++) {
        int r = 4 * rt + i;
        float2 p0 = upk(acc1[i][0]), p1 = upk(acc1[i][1]);
        float4 v;
        v.x = (4 * ct + 0 <= r) ? p0.x : 0.f;
        v.y = (4 * ct + 1 <= r) ? p0.y : 0.f;
        v.z = (4 * ct + 2 <= r) ? p1.x : 0.f;
        v.w = (4 * ct + 3 <= r) ? p1.y : 0.f;
        *(float4*)&S_s[r * 64 + 4 * ct] = v;
    }
    for (int i = tid; i < 1024; i += 256)
        ((float4*)kT_s)[i] = ((const float4*)vp_g)[i];
    __syncthreads();

#pragma unroll
    for (int k = 0; k < 64; k += 4)
        micro4p<64, 64>(S_s, kT_s, 4 * rt, 4 * ct, k, acc);

    int b = bh >> 3, h = bh & 7;
#pragma unroll
    for (int i = 0; i < 4; i++) {
        int s = c * 64 + 4 * rt + i;
        float2 p0 = upk(acc[i][0]), p1 = upk(acc[i][1]);
        *(float4*)&g_attn[((size_t)b * SEQ + s) * DMODEL + h * 64 + 4 * ct] =
            make_float4(p0.x, p0.y, p1.x, p1.y);
    }
}

// ---------------- K4a: fc split-k partial GEMM, 128x128 tiles, 8x8/thread ----------------
__global__ void __launch_bounds__(256) fc_split_kernel(const float* __restrict__ Wfc) {
    __shared__ float A_s[128 * 16];
    __shared__ float Bt_s[16 * 128];   // [e][o]
    int tid = threadIdx.x;
    int r0 = blockIdx.x * 128, o0 = blockIdx.y * 128;
    int kbase = blockIdx.z * 256;
    int rt = tid >> 4, ct = tid & 15;
    u64 acc[8][4] = {};
    for (int kp = 0; kp < 256; kp += 16) {
        for (int i = tid; i < 512; i += 256) {
            int r = i >> 2, kk4 = (i & 3) * 4;
            *(float4*)&A_s[r * 16 + kk4] =
                *(const float4*)&g_attn[(size_t)(r0 + r) * DMODEL + kbase + kp + kk4];
        }
        for (int i = tid; i < 512; i += 256) {
            int o = i >> 2, ee4 = (i & 3) * 4;
            float4 w = *(const float4*)&Wfc[(size_t)(o0 + o) * DMODEL + kbase + kp + ee4];
            Bt_s[(ee4 + 0) * 128 + o] = w.x;
            Bt_s[(ee4 + 1) * 128 + o] = w.y;
            Bt_s[(ee4 + 2) * 128 + o] = w.z;
            Bt_s[(ee4 + 3) * 128 + o] = w.w;
        }
        __syncthreads();
#pragma unroll
        for (int k = 0; k < 16; k += 4)
            micro88p<16, 128>(A_s, Bt_s, 8 * rt, 8 * ct, k, acc);
        __syncthreads();
    }
    float* outp = g_fcp[blockIdx.z];
#pragma unroll
    for (int i = 0; i < 8; i++) {
        int r = r0 + 8 * rt + i;
        float2 p0 = upk(acc[i][0]), p1 = upk(acc[i][1]);
        float2 p2 = upk(acc[i][2]), p3 = upk(acc[i][3]);
        *(float4*)&outp[(size_t)r * DMODEL + o0 + 8 * ct]     = make_float4(p0.x, p0.y, p1.x, p1.y);
        *(float4*)&outp[(size_t)r * DMODEL + o0 + 8 * ct + 4] = make_float4(p2.x, p2.y, p3.x, p3.y);
    }
}

// ---------------- K4b: reduce split-k partials + bias ----------------
__global__ void fc_reduce_kernel(const float* __restrict__ bfc, float* __restrict__ out) {
    int idx = blockIdx.x * 512 + threadIdx.x;   // float4 index
#pragma unroll
    for (int rep = 0; rep < 2; rep++, idx += 256) {
        int o = (idx * 4) & (DMODEL - 1);
        float4 a = ((const float4*)g_fcp[0])[idx];
        float4 b = ((const float4*)g_fcp[1])[idx];
        float4 c = *(const float4*)&bfc[o];
        ((float4*)out)[idx] = make_float4(a.x + b.x + c.x, a.y + b.y + c.y,
                                          a.z + b.z + c.z, a.w + b.w + c.w);
    }
}

// ---------------- launch ----------------
extern "C" void kernel_launch(void* const* d_in, const int* in_sizes, int n_in,
                              void* d_out, int out_size) {
    (void)in_sizes; (void)n_in; (void)out_size;
    const float* q    = (const float*)d_in[0];
    const float* k    = (const float*)d_in[1];
    const float* v    = (const float*)d_in[2];
    const float* Wq   = (const float*)d_in[3];
    const float* bq   = (const float*)d_in[4];
    const float* Wk   = (const float*)d_in[5];
    const float* bk   = (const float*)d_in[6];
    const float* Wv   = (const float*)d_in[7];
    const float* bv   = (const float*)d_in[8];
    const float* orfq = (const float*)d_in[9];
    const float* orfk = (const float*)d_in[10];
    const float* Wfc  = (const float*)d_in[11];
    const float* bfc  = (const float*)d_in[12];
    float* out = (float*)d_out;

    prep_kernel<<<2, 256>>>(Wq, bq, Wk, bk, orfq, orfk);
    feature_kernel<<<dim3(NROWS / 128, 3), 256>>>(q, k, v, Wv, bv);
    chunk_partial_kernel<<<dim3(BH, NCH), 256>>>();
    prefix_kernel<<<128, 256>>>();
    chunk_out_fused<<<dim3(BH, NCH), 256>>>();
    fc_split_kernel<<<dim3(2048 / 128, DMODEL / 128, 2), 256>>>(Wfc);
    fc_reduce_kernel<<<(BATCH * SEQ * DMODEL / 4) / 512, 256>>>(bfc, out);
}

// round 7
// speedup vs baseline: 2.4873x; 1.0694x over previous
#include <cuda_runtime.h>

#define BATCH   2
#define SEQ     1024
#define HEADS   8
#define DEP     64
#define NF      64
#define BH      (BATCH*HEADS)   // 16
#define DMODEL  512
#define CHUNK   64
#define NCH     (SEQ/CHUNK)     // 16

typedef unsigned long long u64;

// ---------------- scratch (static device globals; no allocation) ----------------
__device__ float g_Mqt[DEP*NF];              // Mq transposed: [d][f]
__device__ float g_Mkt[DEP*NF];              // Mk transposed: [d][f]
__device__ float g_Wvt[DEP*DEP];             // Wv transposed: [d][e]
__device__ float g_cbq[NF];
__device__ float g_cbk[NF];
__device__ float g_pS[BH*NCH*NF*DEP];        // per-chunk sum of kf ⊗ vp
__device__ float g_pK[BH*NCH*NF];            // per-chunk sum of kf
__device__ float g_attn[BATCH*SEQ*DMODEL];   // attention out, [b][s][h*64+d]
__device__ float g_fcp[2][BATCH*SEQ*DMODEL]; // split-k partials for fc
__device__ unsigned g_done[BH];              // per-bh chunk-completion bitmask

// ---------------- packed f32x2 helpers (sm_103a FFMA2) ----------------
__device__ __forceinline__ u64 pk2(float x) {
    u64 r; asm("mov.b64 %0, {%1,%1};" : "=l"(r) : "f"(x)); return r;
}
__device__ __forceinline__ u64 pk2b(float x, float y) {
    u64 r; asm("mov.b64 %0, {%1,%2};" : "=l"(r) : "f"(x), "f"(y)); return r;
}
__device__ __forceinline__ void fma2(u64& d, u64 a, u64 b) {
    asm("fma.rn.f32x2 %0, %1, %2, %0;" : "+l"(d) : "l"(a), "l"(b));
}
__device__ __forceinline__ float2 upk(u64 v) {
    float2 f; asm("mov.b64 {%0,%1}, %2;" : "=f"(f.x), "=f"(f.y) : "l"(v)); return f;
}

// ---------------- 4x4 micro-kernel (prep) ----------------
template<int LDA, int LDB>
__device__ __forceinline__ void micro4p(const float* As, const float* Bs,
                                        int rb, int cb, int k, u64 acc[4][2]) {
    float a[4][4];
#pragma unroll
    for (int i = 0; i < 4; i++)
        *(float4*)a[i] = *(const float4*)&As[(rb + i) * LDA + k];
    u64 b[4][2];
#pragma unroll
    for (int kk = 0; kk < 4; kk++)
        *(ulonglong2*)b[kk] = *(const ulonglong2*)&Bs[(k + kk) * LDB + cb];
#pragma unroll
    for (int kk = 0; kk < 4; kk++)
#pragma unroll
        for (int i = 0; i < 4; i++) {
            u64 ad = pk2(a[i][kk]);
            fma2(acc[i][0], ad, b[kk][0]);
            fma2(acc[i][1], ad, b[kk][1]);
        }
}

// ---------------- 8x4 micro-kernel (mega): 1.5 B/MAC ----------------
template<int LDA, int LDB>
__device__ __forceinline__ void micro84p(const float* As, const float* Bs,
                                         int rb, int cb, int k, u64 acc[8][2]) {
    float a[8][4];
#pragma unroll
    for (int i = 0; i < 8; i++)
        *(float4*)a[i] = *(const float4*)&As[(rb + i) * LDA + k];
#pragma unroll
    for (int kk = 0; kk < 4; kk++) {
        u64 b[2];
        *(ulonglong2*)b = *(const ulonglong2*)&Bs[(k + kk) * LDB + cb];
#pragma unroll
        for (int i = 0; i < 8; i++) {
            u64 ad = pk2(a[i][kk]);
            fma2(acc[i][0], ad, b[0]);
            fma2(acc[i][1], ad, b[1]);
        }
    }
}

// ---------------- 8x8 micro-kernel (fc): 1.0 B/MAC ----------------
template<int LDA, int LDB>
__device__ __forceinline__ void micro88p(const float* As, const float* Bs,
                                         int rb, int cb, int k, u64 acc[8][4]) {
    float a[8][4];
#pragma unroll
    for (int i = 0; i < 8; i++)
        *(float4*)a[i] = *(const float4*)&As[(rb + i) * LDA + k];
#pragma unroll
    for (int kk = 0; kk < 4; kk++) {
        u64 b[4];
        *(ulonglong2*)&b[0] = *(const ulonglong2*)&Bs[(k + kk) * LDB + cb];
        *(ulonglong2*)&b[2] = *(const ulonglong2*)&Bs[(k + kk) * LDB + cb + 4];
#pragma unroll
        for (int i = 0; i < 8; i++) {
            u64 ad = pk2(a[i][kk]);
            fma2(acc[i][0], ad, b[0]);
            fma2(acc[i][1], ad, b[1]);
            fma2(acc[i][2], ad, b[2]);
            fma2(acc[i][3], ad, b[3]);
        }
    }
}

// ---------------- K0: fold Linear+ORF (transposed), transpose Wv, reset flags ----------------
__global__ void prep_kernel(const float* __restrict__ Wq, const float* __restrict__ bq,
                            const float* __restrict__ Wk, const float* __restrict__ bk,
                            const float* __restrict__ orfq, const float* __restrict__ orfk,
                            const float* __restrict__ Wv) {
    int tid = threadIdx.x;
    if (blockIdx.x == 2) {   // Wv^T: g_Wvt[d][e] = Wv[e][d]
        for (int i = tid; i < 4096; i += 256) {
            int e = i >> 6, d = i & 63;
            g_Wvt[d * 64 + e] = Wv[i];
        }
        return;
    }
    __shared__ float orf_s[4096];   // [f][e]
    __shared__ float W_s[4096];     // [e][d]
    __shared__ float b_s[64];
    const float norm = 0.35355339059327379f;  // 64^(-0.25)
    int s = blockIdx.x;
    const float* orf = s ? orfk : orfq;
    const float* W   = s ? Wk   : Wq;
    const float* bb  = s ? bk   : bq;
    float* Mt = s ? g_Mkt : g_Mqt;
    float* cb = s ? g_cbk : g_cbq;
    if (s == 0 && tid < BH) g_done[tid] = 0u;   // reset completion flags each launch
    for (int i = tid; i < 1024; i += 256) {
        ((float4*)orf_s)[i] = ((const float4*)orf)[i];
        ((float4*)W_s)[i]   = ((const float4*)W)[i];
    }
    if (tid < 64) b_s[tid] = bb[tid];
    __syncthreads();

    int rt = tid >> 4, ct = tid & 15;
    u64 acc[4][2] = {};
#pragma unroll
    for (int k = 0; k < 64; k += 4)
        micro4p<64, 64>(orf_s, W_s, 4 * rt, 4 * ct, k, acc);
#pragma unroll
    for (int i = 0; i < 4; i++) {
        float2 p0 = upk(acc[i][0]), p1 = upk(acc[i][1]);
        float vals[4] = { p0.x, p0.y, p1.x, p1.y };
#pragma unroll
        for (int j = 0; j < 4; j++)          // transposed store: Mt[d][f]
            Mt[(4 * ct + j) * 64 + (4 * rt + i)] = norm * vals[j];
    }
    if (tid < 64) {
        float a = 0.f;
#pragma unroll
        for (int e = 0; e < 64; e++) a += orf_s[tid * 64 + e] * b_s[e];
        cb[tid] = norm * a;
    }
}

// ---------------- K1 (mega): features + partials + device-sync prefix + output ----------------
// smem layout (floats): X_s[0..4096) scratch, w_s[4096..8192) weights,
// qt_s[8192..12288), kf_s[12288..16384), vp_s[16384..20480)  = 80KB
__global__ void __launch_bounds__(128) mega_kernel(const float* __restrict__ qin,
                                                   const float* __restrict__ kin,
                                                   const float* __restrict__ vin,
                                                   const float* __restrict__ bv) {
    extern __shared__ float sm[];
    float* X_s  = sm;
    float* w_s  = sm + 4096;
    float* qt_s = sm + 8192;
    float* kf_s = sm + 12288;
    float* vp_s = sm + 16384;
    __shared__ float part_s[128];

    int bh = blockIdx.x, c = blockIdx.y, tid = threadIdx.x;
    int b = bh >> 3, h = bh & 7;
    int rt = tid >> 4, ct = tid & 15;

    // ---- P0: feature GEMMs for this chunk (q, k, v) ----
#pragma unroll 1
    for (int str = 0; str < 3; str++) {
        const float* inp  = (str == 0) ? qin   : (str == 1) ? kin   : vin;
        const float* wt   = (str == 0) ? g_Mqt : (str == 1) ? g_Mkt : g_Wvt;
        const float* bias = (str == 0) ? g_cbq : (str == 1) ? g_cbk : bv;
        float* dst        = (str == 0) ? qt_s  : (str == 1) ? kf_s  : vp_s;
        const float4* ing = (const float4*)(inp + ((size_t)(b * SEQ + c * CHUNK)) * DMODEL + h * DEP);
        for (int i = tid; i < 1024; i += 128)
            ((float4*)X_s)[i] = ing[(i >> 4) * 128 + (i & 15)];   // [t][d]
        for (int i = tid; i < 1024; i += 128)
            ((float4*)w_s)[i] = ((const float4*)wt)[i];           // [d][out]
        __syncthreads();
        u64 acc[8][2];
        {
            u64 b0 = pk2b(bias[4 * ct + 0], bias[4 * ct + 1]);
            u64 b1 = pk2b(bias[4 * ct + 2], bias[4 * ct + 3]);
#pragma unroll
            for (int i = 0; i < 8; i++) { acc[i][0] = b0; acc[i][1] = b1; }
        }
#pragma unroll
        for (int k = 0; k < 64; k += 4)
            micro84p<64, 64>(X_s, w_s, 8 * rt, 4 * ct, k, acc);
#pragma unroll
        for (int i = 0; i < 8; i++) {
            int row = 8 * rt + i;
            float2 p0 = upk(acc[i][0]), p1 = upk(acc[i][1]);
            float4 vv = make_float4(p0.x, p0.y, p1.x, p1.y);
            if (str < 2) {
                vv.x = fmaxf(vv.x, 0.f) + 0.001f;
                vv.y = fmaxf(vv.y, 0.f) + 0.001f;
                vv.z = fmaxf(vv.z, 0.f) + 0.001f;
                vv.w = fmaxf(vv.w, 0.f) + 0.001f;
            }
            *(float4*)&dst[row * 64 + 4 * ct] = vv;
        }
        __syncthreads();
    }

    // ---- P1: kf^T into X_s, pK partials, pS GEMM; publish ----
    {
        int u = tid >> 1, fb = (tid & 1) * 32;
#pragma unroll
        for (int j = 0; j < 32; j += 4) {
            float4 w = *(const float4*)&kf_s[u * 64 + fb + j];
            X_s[(fb + j + 0) * 64 + u] = w.x;
            X_s[(fb + j + 1) * 64 + u] = w.y;
            X_s[(fb + j + 2) * 64 + u] = w.z;
            X_s[(fb + j + 3) * 64 + u] = w.w;
        }
    }
    {
        int f = tid & 63, hlf = tid >> 6;
        float ps = 0.f;
        for (int u = hlf * 32; u < hlf * 32 + 32; u++) ps += kf_s[u * 64 + f];
        part_s[hlf * 64 + f] = ps;
    }
    __syncthreads();
    {
        u64 acc2[8][2] = {};
#pragma unroll
        for (int k = 0; k < 64; k += 4)
            micro84p<64, 64>(X_s, vp_s, 8 * rt, 4 * ct, k, acc2);
        float* pS_out = g_pS + ((size_t)bh * NCH + c) * 4096;
#pragma unroll
        for (int i = 0; i < 8; i++) {
            float2 p0 = upk(acc2[i][0]), p1 = upk(acc2[i][1]);
            *(float4*)&pS_out[(8 * rt + i) * 64 + 4 * ct] = make_float4(p0.x, p0.y, p1.x, p1.y);
        }
        if (tid < 64)
            g_pK[((size_t)bh * NCH + c) * 64 + tid] = part_s[tid] + part_s[64 + tid];
    }
    __threadfence();
    __syncthreads();
    if (tid == 0) atomicOr(&g_done[bh], 1u << c);

    // ---- P2: wait for all earlier chunks of this bh ----
    unsigned need = (1u << c) - 1u;
    if (tid == 0 && need) {
        while ((atomicOr(&g_done[bh], 0u) & need) != need) __nanosleep(64);
    }
    __syncthreads();

    // ---- P3: qt = qf / cumsum(kf) ----
    {
        int f = tid & 63, hlf = tid >> 6;
        float base = 0.f;
        for (int c2 = 0; c2 < c; c2++)
            base += g_pK[((size_t)bh * NCH + c2) * 64 + f];
        float kc = base + (hlf ? part_s[f] : 0.f);   // part_s still holds half-sums
        for (int u = hlf * 32; u < hlf * 32 + 32; u++) {
            kc += kf_s[u * 64 + f];
            qt_s[u * 64 + f] = __fdividef(qt_s[u * 64 + f], kc);
        }
    }
    __syncthreads();

    // ---- P4: preS rebuild (batched MLP loads) + inter-chunk GEMM ----
    u64 acc[8][2] = {};
    if (c > 0) {
        float4 a4[8];
#pragma unroll
        for (int j = 0; j < 8; j++) a4[j] = make_float4(0.f, 0.f, 0.f, 0.f);
        const float4* base4 = (const float4*)(g_pS + (size_t)bh * NCH * 4096);
        for (int c2 = 0; c2 < c; c2++) {
#pragma unroll
            for (int j = 0; j < 8; j++) {
                float4 t = base4[c2 * 1024 + j * 128 + tid];
                a4[j].x += t.x; a4[j].y += t.y; a4[j].z += t.z; a4[j].w += t.w;
            }
        }
#pragma unroll
        for (int j = 0; j < 8; j++) ((float4*)X_s)[j * 128 + tid] = a4[j];
        __syncthreads();
#pragma unroll
        for (int k = 0; k < 64; k += 4)
            micro84p<64, 64>(qt_s, X_s, 8 * rt, 4 * ct, k, acc);
    }
    __syncthreads();

    // ---- P5: intra-chunk (scores, mask, @vp) ----
    {   // rebuild kf^T in X_s
        int u = tid >> 1, fb = (tid & 1) * 32;
#pragma unroll
        for (int j = 0; j < 32; j += 4) {
            float4 w = *(const float4*)&kf_s[u * 64 + fb + j];
            X_s[(fb + j + 0) * 64 + u] = w.x;
            X_s[(fb + j + 1) * 64 + u] = w.y;
            X_s[(fb + j + 2) * 64 + u] = w.z;
            X_s[(fb + j + 3) * 64 + u] = w.w;
        }
    }
    __syncthreads();
    u64 acc1[8][2] = {};
#pragma unroll
    for (int k = 0; k < 64; k += 4)
        micro84p<64, 64>(qt_s, X_s, 8 * rt, 4 * ct, k, acc1);
    __syncthreads();
#pragma unroll
    for (int i = 0; i < 8; i++) {
        int r = 8 * rt + i;
        float2 p0 = upk(acc1[i][0]), p1 = upk(acc1[i][1]);
        float4 vv;
        vv.x = (4 * ct + 0 <= r) ? p0.x : 0.f;
        vv.y = (4 * ct + 1 <= r) ? p0.y : 0.f;
        vv.z = (4 * ct + 2 <= r) ? p1.x : 0.f;
        vv.w = (4 * ct + 3 <= r) ? p1.y : 0.f;
        *(float4*)&X_s[r * 64 + 4 * ct] = vv;
    }
    __syncthreads();
#pragma unroll
    for (int k = 0; k < 64; k += 4)
        micro84p<64, 64>(X_s, vp_s, 8 * rt, 4 * ct, k, acc);

#pragma unroll
    for (int i = 0; i < 8; i++) {
        int s = c * CHUNK + 8 * rt + i;
        float2 p0 = upk(acc[i][0]), p1 = upk(acc[i][1]);
        *(float4*)&g_attn[((size_t)b * SEQ + s) * DMODEL + h * DEP + 4 * ct] =
            make_float4(p0.x, p0.y, p1.x, p1.y);
    }
}

// ---------------- K2: fc split-k partial GEMM, 128x128 tiles, 8x8/thread ----------------
__global__ void __launch_bounds__(256) fc_split_kernel(const float* __restrict__ Wfc) {
    __shared__ float A_s[128 * 16];
    __shared__ float Bt_s[16 * 128];   // [e][o]
    int tid = threadIdx.x;
    int r0 = blockIdx.x * 128, o0 = blockIdx.y * 128;
    int kbase = blockIdx.z * 256;
    int rt = tid >> 4, ct = tid & 15;
    u64 acc[8][4] = {};
    for (int kp = 0; kp < 256; kp += 16) {
        for (int i = tid; i < 512; i += 256) {
            int r = i >> 2, kk4 = (i & 3) * 4;
            *(float4*)&A_s[r * 16 + kk4] =
                *(const float4*)&g_attn[(size_t)(r0 + r) * DMODEL + kbase + kp + kk4];
        }
        for (int i = tid; i < 512; i += 256) {
            int o = i >> 2, ee4 = (i & 3) * 4;
            float4 w = *(const float4*)&Wfc[(size_t)(o0 + o) * DMODEL + kbase + kp + ee4];
            Bt_s[(ee4 + 0) * 128 + o] = w.x;
            Bt_s[(ee4 + 1) * 128 + o] = w.y;
            Bt_s[(ee4 + 2) * 128 + o] = w.z;
            Bt_s[(ee4 + 3) * 128 + o] = w.w;
        }
        __syncthreads();
#pragma unroll
        for (int k = 0; k < 16; k += 4)
            micro88p<16, 128>(A_s, Bt_s, 8 * rt, 8 * ct, k, acc);
        __syncthreads();
    }
    float* outp = g_fcp[blockIdx.z];
#pragma unroll
    for (int i = 0; i < 8; i++) {
        int r = r0 + 8 * rt + i;
        float2 p0 = upk(acc[i][0]), p1 = upk(acc[i][1]);
        float2 p2 = upk(acc[i][2]), p3 = upk(acc[i][3]);
        *(float4*)&outp[(size_t)r * DMODEL + o0 + 8 * ct]     = make_float4(p0.x, p0.y, p1.x, p1.y);
        *(float4*)&outp[(size_t)r * DMODEL + o0 + 8 * ct + 4] = make_float4(p2.x, p2.y, p3.x, p3.y);
    }
}

// ---------------- K3: reduce split-k partials + bias ----------------
__global__ void fc_reduce_kernel(const float* __restrict__ bfc, float* __restrict__ out) {
    int idx = blockIdx.x * 512 + threadIdx.x;   // float4 index
#pragma unroll
    for (int rep = 0; rep < 2; rep++, idx += 256) {
        int o = (idx * 4) & (DMODEL - 1);
        float4 a = ((const float4*)g_fcp[0])[idx];
        float4 b = ((const float4*)g_fcp[1])[idx];
        float4 c = *(const float4*)&bfc[o];
        ((float4*)out)[idx] = make_float4(a.x + b.x + c.x, a.y + b.y + c.y,
                                          a.z + b.z + c.z, a.w + b.w + c.w);
    }
}

// ---------------- launch ----------------
extern "C" void kernel_launch(void* const* d_in, const int* in_sizes, int n_in,
                              void* d_out, int out_size) {
    (void)in_sizes; (void)n_in; (void)out_size;
    const float* q    = (const float*)d_in[0];
    const float* k    = (const float*)d_in[1];
    const float* v    = (const float*)d_in[2];
    const float* Wq   = (const float*)d_in[3];
    const float* bq   = (const float*)d_in[4];
    const float* Wk   = (const float*)d_in[5];
    const float* bk   = (const float*)d_in[6];
    const float* Wv   = (const float*)d_in[7];
    const float* bv   = (const float*)d_in[8];
    const float* orfq = (const float*)d_in[9];
    const float* orfk = (const float*)d_in[10];
    const float* Wfc  = (const float*)d_in[11];
    const float* bfc  = (const float*)d_in[12];
    float* out = (float*)d_out;

    static bool attr_set = false;
    if (!attr_set) {
        cudaFuncSetAttribute(mega_kernel, cudaFuncAttributeMaxDynamicSharedMemorySize, 81920);
        attr_set = true;
    }

    prep_kernel<<<3, 256>>>(Wq, bq, Wk, bk, orfq, orfk, Wv);
    mega_kernel<<<dim3(BH, NCH), 128, 81920>>>(q, k, v, bv);
    fc_split_kernel<<<dim3(2048 / 128, DMODEL / 128, 2), 256>>>(Wfc);
    fc_reduce_kernel<<<(BATCH * SEQ * DMODEL / 4) / 512, 256>>>(bfc, out);
}